// round 11
// baseline (speedup 1.0000x reference)
#include <cuda_runtime.h>
#include <cuda_bf16.h>
#include <cstdint>

// ---------------------------------------------------------------------------
// GatedAttentionUnit: S=2048, B=4, E=1024, Z=128, H=2048
// R11: R10 inner-loop (fragment-reuse split-2: hh+hl+lh) but 512 threads,
//      warp grid 4x4, per-warp 32x32 tile -> 4 warps/SMSP (occ 25%) to hide
//      LDS latency. Same 64-wide chunks, single buffer, 69.6 KB smem.
// ---------------------------------------------------------------------------

#define S_LEN 2048
#define BSZ 4
#define EDIM 1024
#define ZDIM 128
#define HDIM 2048
#define GEMM_THREADS 512
#define SCORE_THREADS 256

// smem tile: 128 rows x 128 bf16 (hi 64 | lo 64), row stride 68 words
// (68 % 32 == 4 -> fragment LDS bank == lane -> conflict-free)
#define ROW_W 68
#define TILE_W (128 * ROW_W)            // words per tile
#define SMEM_DYN_BYTES (2 * TILE_W * 4) // A + B = 69632 B

// Scratch (device globals: allocation-free per harness rules)
__device__ float d_u   [(size_t)S_LEN * BSZ * HDIM];
__device__ float d_vT  [(size_t)BSZ * HDIM * S_LEN];
__device__ float d_q   [(size_t)BSZ * S_LEN * ZDIM];
__device__ float d_kk  [(size_t)BSZ * S_LEN * ZDIM];
__device__ float d_attn[(size_t)BSZ * S_LEN * S_LEN];
__device__ float d_g   [(size_t)S_LEN * BSZ * HDIM];

// ---------------------------------------------------------------------------
__device__ __forceinline__ void mma16816(float* d, const uint32_t* a, const uint32_t* b) {
    asm volatile(
        "mma.sync.aligned.m16n8k16.row.col.f32.bf16.bf16.f32 "
        "{%0,%1,%2,%3}, {%4,%5,%6,%7}, {%8,%9}, {%0,%1,%2,%3};"
        : "+f"(d[0]), "+f"(d[1]), "+f"(d[2]), "+f"(d[3])
        : "r"(a[0]), "r"(a[1]), "r"(a[2]), "r"(a[3]), "r"(b[0]), "r"(b[1]));
}

__device__ __forceinline__ uint32_t pack_hi(float f0, float f1) {
    __nv_bfloat16 h0 = __float2bfloat16_rn(f0);
    __nv_bfloat16 h1 = __float2bfloat16_rn(f1);
    return (uint32_t)__bfloat16_as_ushort(h0) | ((uint32_t)__bfloat16_as_ushort(h1) << 16);
}
__device__ __forceinline__ uint32_t pack_lo(float f0, float f1) {
    __nv_bfloat16 h0 = __float2bfloat16_rn(f0);
    __nv_bfloat16 h1 = __float2bfloat16_rn(f1);
    __nv_bfloat16 l0 = __float2bfloat16_rn(f0 - __bfloat162float(h0));
    __nv_bfloat16 l1 = __float2bfloat16_rn(f1 - __bfloat162float(h1));
    return (uint32_t)__bfloat16_as_ushort(l0) | ((uint32_t)__bfloat16_as_ushort(l1) << 16);
}

// Load one 64-fp32-wide K chunk of A and B tiles into registers (4+4 float4)
__device__ __forceinline__ void load_chunk(
    const float* __restrict__ A, int lda,
    const float* __restrict__ B, int ldb, int c, float4 fs[8])
{
    const int tid = threadIdx.x;
#pragma unroll
    for (int u = 0; u < 2; ++u) {
        int idx = u * GEMM_THREADS + tid;
        int row = idx >> 3, grp = idx & 7;
        const float* pa = A + (size_t)row * lda + c * 64 + grp * 8;
        fs[u * 2 + 0] = *(const float4*)pa;
        fs[u * 2 + 1] = *(const float4*)(pa + 4);
        const float* pb = B + (size_t)row * ldb + c * 64 + grp * 8;
        fs[u * 2 + 4] = *(const float4*)pb;
        fs[u * 2 + 5] = *(const float4*)(pb + 4);
    }
}

// Convert registers -> [hi|lo] bf16 smem tiles
__device__ __forceinline__ void store_chunk(const float4 fs[8],
                                            uint32_t* Aw, uint32_t* Bw)
{
    const int tid = threadIdx.x;
#pragma unroll
    for (int u = 0; u < 2; ++u) {
        int idx = u * GEMM_THREADS + tid;
        int row = idx >> 3, grp = idx & 7;
        const float4 a0 = fs[u * 2 + 0], a1 = fs[u * 2 + 1];
        const float4 b0 = fs[u * 2 + 4], b1 = fs[u * 2 + 5];
        uint32_t* ah = Aw + row * ROW_W + grp * 4;
        *(uint4*)ah = make_uint4(pack_hi(a0.x, a0.y), pack_hi(a0.z, a0.w),
                                 pack_hi(a1.x, a1.y), pack_hi(a1.z, a1.w));
        *(uint4*)(ah + 32) = make_uint4(pack_lo(a0.x, a0.y), pack_lo(a0.z, a0.w),
                                        pack_lo(a1.x, a1.y), pack_lo(a1.z, a1.w));
        uint32_t* bh = Bw + row * ROW_W + grp * 4;
        *(uint4*)bh = make_uint4(pack_hi(b0.x, b0.y), pack_hi(b0.z, b0.w),
                                 pack_hi(b1.x, b1.y), pack_hi(b1.z, b1.w));
        *(uint4*)(bh + 32) = make_uint4(pack_lo(b0.x, b0.y), pack_lo(b0.z, b0.w),
                                        pack_lo(b1.x, b1.y), pack_lo(b1.z, b1.w));
    }
}

// ---------------------------------------------------------------------------
// Core GEMM: acc(128x128) = A(128xK) * B(128xK)^T, fp32 in, fp32 accum.
// 16 warps as 4(M) x 4(N); per-warp 32x32 via 2x4 m16n8k16 tiles.
// Split-2 with fragment reuse: per ks load B-hi, B-lo, A-hi -> hh, hl;
// overwrite A-lo -> lh.
// ---------------------------------------------------------------------------
extern __shared__ uint32_t smw[];

__device__ __forceinline__ void mma_gemm(
    const float* __restrict__ A, int lda,
    const float* __restrict__ B, int ldb,
    int nChunks, float acc[2][4][4])
{
    uint32_t* Aw = smw;
    uint32_t* Bw = smw + TILE_W;
    const int tid = threadIdx.x;
    const int lane = tid & 31, wid = tid >> 5;
    const int g = lane >> 2, tg = lane & 3;
    const int wm = wid & 3, wn = wid >> 2;
    const int arow = wm * 32 + g;
    const int brow = wn * 32 + g;

    float4 fs[8];
    load_chunk(A, lda, B, ldb, 0, fs);

    for (int c = 0; c < nChunks; ++c) {
        __syncthreads();
        store_chunk(fs, Aw, Bw);
        __syncthreads();
        if (c + 1 < nChunks) load_chunk(A, lda, B, ldb, c + 1, fs);

        // 4 ks-groups of K=16; per group: bh, bl, A-hi (hh, hl), A-lo (lh)
#pragma unroll 1
        for (int ks = 0; ks < 4; ++ks) {
            uint32_t bh[4][2], bl[4][2], av[2][4];
#pragma unroll
            for (int ni = 0; ni < 4; ++ni) {
                const uint32_t* pB = Bw + (brow + ni * 8) * ROW_W + ks * 8 + tg;
                bh[ni][0] = pB[0];
                bh[ni][1] = pB[4];
                bl[ni][0] = pB[32];
                bl[ni][1] = pB[36];
            }
#pragma unroll
            for (int mi = 0; mi < 2; ++mi) {
                const uint32_t* pA = Aw + (arow + mi * 16) * ROW_W + ks * 8 + tg;
                av[mi][0] = pA[0];
                av[mi][1] = pA[8 * ROW_W];
                av[mi][2] = pA[4];
                av[mi][3] = pA[8 * ROW_W + 4];
            }
#pragma unroll
            for (int mi = 0; mi < 2; ++mi)
#pragma unroll
                for (int ni = 0; ni < 4; ++ni)
                    mma16816(acc[mi][ni], av[mi], bh[ni]);
#pragma unroll
            for (int mi = 0; mi < 2; ++mi)
#pragma unroll
                for (int ni = 0; ni < 4; ++ni)
                    mma16816(acc[mi][ni], av[mi], bl[ni]);
#pragma unroll
            for (int mi = 0; mi < 2; ++mi) {
                const uint32_t* pA = Aw + (arow + mi * 16) * ROW_W + 32 + ks * 8 + tg;
                av[mi][0] = pA[0];
                av[mi][1] = pA[8 * ROW_W];
                av[mi][2] = pA[4];
                av[mi][3] = pA[8 * ROW_W + 4];
            }
#pragma unroll
            for (int mi = 0; mi < 2; ++mi)
#pragma unroll
                for (int ni = 0; ni < 4; ++ni)
                    mma16816(acc[mi][ni], av[mi], bh[ni]);
        }
    }
}

__device__ __forceinline__ float silu(float v) { return v / (1.0f + __expf(-v)); }

// Per-thread element coordinates inside the 128x128 tile:
//   r = wm*32 + mi*16 + g + (e>=2 ? 8 : 0)
//   c = wn*32 + ni*8 + tg*2 + (e&1)

// ---------------------------------------------------------------------------
// K1: proj = silu(x @ Wp^T + bp); split into u / vT / q / k
// ---------------------------------------------------------------------------
__global__ void __launch_bounds__(GEMM_THREADS, 1)
k_proj_t(const float* __restrict__ X, const float* __restrict__ W,
         const float* __restrict__ pb, const float* __restrict__ gamma,
         const float* __restrict__ beta)
{
    const int bx = blockIdx.x, by = blockIdx.y;
    float acc[2][4][4] = {};
    mma_gemm(X + (size_t)by * 128 * EDIM, EDIM,
             W + (size_t)bx * 128 * EDIM, EDIM, EDIM / 64, acc);

    const int lane = threadIdx.x & 31, wid = threadIdx.x >> 5;
    const int g = lane >> 2, tg = lane & 3;
    const int wm = wid & 3, wn = wid >> 2;
#pragma unroll
    for (int mi = 0; mi < 2; ++mi) {
#pragma unroll
        for (int ni = 0; ni < 4; ++ni) {
#pragma unroll
            for (int e = 0; e < 4; ++e) {
                int r = by * 128 + wm * 32 + mi * 16 + g + ((e >> 1) ? 8 : 0);
                int cg = bx * 128 + wn * 32 + ni * 8 + tg * 2 + (e & 1);
                float v = silu(acc[mi][ni][e] + pb[cg]);
                int s = r >> 2, b = r & 3;
                if (bx < 16) {
                    d_u[(size_t)r * HDIM + cg] = v;
                } else if (bx < 32) {
                    int h = cg - HDIM;
                    d_vT[((size_t)b * HDIM + h) * S_LEN + s] = v;
                } else {
                    int zi = cg - 2 * HDIM;
                    size_t qi = ((size_t)b * S_LEN + s) * ZDIM + zi;
                    d_q[qi]  = v * gamma[zi]        + beta[zi];
                    d_kk[qi] = v * gamma[ZDIM + zi] + beta[ZDIM + zi];
                }
            }
        }
    }
}

// ---------------------------------------------------------------------------
// K2: scores = relu(q k^T / S + bias)^2, causal (fp32 FFMA, small)
// ---------------------------------------------------------------------------
#define BK 16
__global__ void __launch_bounds__(SCORE_THREADS, 2)
k_score(const float* __restrict__ rpb)
{
    const int by = blockIdx.y, bx = blockIdx.x, b = blockIdx.z;
    if (bx > by) return;
    __shared__ float As[BK][129];
    __shared__ float Bs[BK][129];
    float acc[8][8] = {};
    const float* Ag0 = d_q  + ((size_t)b * S_LEN + by * 128) * ZDIM;
    const float* Bg0 = d_kk + ((size_t)b * S_LEN + bx * 128) * ZDIM;
    const int tid = threadIdx.x;
    const int lr = tid >> 2, lc = (tid & 3) << 2;
    const float* Ag = Ag0 + lr * ZDIM + lc;
    const float* Bg = Bg0 + lr * ZDIM + lc;
    const int ty = tid >> 4, tx = tid & 15;
    for (int kk = 0; kk < ZDIM / BK; ++kk) {
        float4 a0 = *(const float4*)(Ag);
        float4 a1 = *(const float4*)(Ag + 64 * ZDIM);
        float4 b0 = *(const float4*)(Bg);
        float4 b1 = *(const float4*)(Bg + 64 * ZDIM);
        __syncthreads();
        As[lc + 0][lr] = a0.x; As[lc + 1][lr] = a0.y; As[lc + 2][lr] = a0.z; As[lc + 3][lr] = a0.w;
        As[lc + 0][lr + 64] = a1.x; As[lc + 1][lr + 64] = a1.y; As[lc + 2][lr + 64] = a1.z; As[lc + 3][lr + 64] = a1.w;
        Bs[lc + 0][lr] = b0.x; Bs[lc + 1][lr] = b0.y; Bs[lc + 2][lr] = b0.z; Bs[lc + 3][lr] = b0.w;
        Bs[lc + 0][lr + 64] = b1.x; Bs[lc + 1][lr + 64] = b1.y; Bs[lc + 2][lr + 64] = b1.z; Bs[lc + 3][lr + 64] = b1.w;
        __syncthreads();
#pragma unroll
        for (int k = 0; k < BK; ++k) {
            float ar[8], br[8];
#pragma unroll
            for (int i = 0; i < 8; ++i) ar[i] = As[k][i * 16 + ty];
#pragma unroll
            for (int j = 0; j < 8; ++j) br[j] = Bs[k][j * 16 + tx];
#pragma unroll
            for (int i = 0; i < 8; ++i)
#pragma unroll
                for (int j = 0; j < 8; ++j) acc[i][j] += ar[i] * br[j];
        }
        Ag += BK; Bg += BK;
    }
#pragma unroll
    for (int i = 0; i < 8; ++i) {
#pragma unroll
        for (int j = 0; j < 8; ++j) {
            int r = by * 128 + i * 16 + ty;
            int c = bx * 128 + j * 16 + tx;
            float v = acc[i][j] * (1.0f / (float)S_LEN) + rpb[(S_LEN - 1) + c - r];
            float a = (c > r) ? 0.0f : fmaxf(v, 0.0f);
            d_attn[((size_t)b * S_LEN + r) * S_LEN + c] = a * a;
        }
    }
}

// ---------------------------------------------------------------------------
// K3: g = (attn @ v) * u   (K truncated at diagonal)
// ---------------------------------------------------------------------------
__global__ void __launch_bounds__(GEMM_THREADS, 1)
k_av_t()
{
    const int bx = blockIdx.x, by = blockIdx.y, b = blockIdx.z;
    float acc[2][4][4] = {};
    mma_gemm(d_attn + ((size_t)b * S_LEN + by * 128) * S_LEN, S_LEN,
             d_vT   + ((size_t)b * HDIM + bx * 128) * S_LEN, S_LEN,
             (by + 1) * 2, acc);

    const int lane = threadIdx.x & 31, wid = threadIdx.x >> 5;
    const int g = lane >> 2, tg = lane & 3;
    const int wm = wid & 3, wn = wid >> 2;
#pragma unroll
    for (int mi = 0; mi < 2; ++mi) {
#pragma unroll
        for (int ni = 0; ni < 4; ++ni) {
#pragma unroll
            for (int e = 0; e < 4; ++e) {
                int q = by * 128 + wm * 32 + mi * 16 + g + ((e >> 1) ? 8 : 0);
                int h = bx * 128 + wn * 32 + ni * 8 + tg * 2 + (e & 1);
                size_t idx = ((size_t)q * BSZ + b) * HDIM + h;
                d_g[idx] = acc[mi][ni][e] * d_u[idx];
            }
        }
    }
}

// ---------------------------------------------------------------------------
// K4: out = g @ Wo^T + bo
// ---------------------------------------------------------------------------
__global__ void __launch_bounds__(GEMM_THREADS, 1)
k_out_t(const float* __restrict__ OW, const float* __restrict__ ob,
        float* __restrict__ out)
{
    const int bx = blockIdx.x, by = blockIdx.y;
    float acc[2][4][4] = {};
    mma_gemm(d_g + (size_t)by * 128 * HDIM, HDIM,
             OW + (size_t)bx * 128 * HDIM, HDIM, HDIM / 64, acc);

    const int lane = threadIdx.x & 31, wid = threadIdx.x >> 5;
    const int g = lane >> 2, tg = lane & 3;
    const int wm = wid & 3, wn = wid >> 2;
#pragma unroll
    for (int mi = 0; mi < 2; ++mi) {
#pragma unroll
        for (int ni = 0; ni < 4; ++ni) {
#pragma unroll
            for (int e = 0; e < 4; ++e) {
                int r = by * 128 + wm * 32 + mi * 16 + g + ((e >> 1) ? 8 : 0);
                int c = bx * 128 + wn * 32 + ni * 8 + tg * 2 + (e & 1);
                out[(size_t)r * EDIM + c] = acc[mi][ni][e] + ob[c];
            }
        }
    }
}

// ---------------------------------------------------------------------------
extern "C" void kernel_launch(void* const* d_in, const int* in_sizes, int n_in,
                              void* d_out, int out_size)
{
    const float* x      = (const float*)d_in[0];
    const float* proj_w = (const float*)d_in[2];
    const float* proj_b = (const float*)d_in[3];
    const float* out_w  = (const float*)d_in[4];
    const float* out_b  = (const float*)d_in[5];
    const float* gamma  = (const float*)d_in[6];
    const float* beta   = (const float*)d_in[7];
    const float* rpb    = (const float*)d_in[8];
    float* out = (float*)d_out;

    cudaFuncSetAttribute(k_proj_t, cudaFuncAttributeMaxDynamicSharedMemorySize, SMEM_DYN_BYTES);
    cudaFuncSetAttribute(k_av_t,   cudaFuncAttributeMaxDynamicSharedMemorySize, SMEM_DYN_BYTES);
    cudaFuncSetAttribute(k_out_t,  cudaFuncAttributeMaxDynamicSharedMemorySize, SMEM_DYN_BYTES);

    k_proj_t<<<dim3(33, 64), dim3(GEMM_THREADS), SMEM_DYN_BYTES>>>(x, proj_w, proj_b, gamma, beta);
    k_score <<<dim3(16, 16, 4), dim3(SCORE_THREADS)>>>(rpb);
    k_av_t  <<<dim3(16, 16, 4), dim3(GEMM_THREADS), SMEM_DYN_BYTES>>>();
    k_out_t <<<dim3(8, 64), dim3(GEMM_THREADS), SMEM_DYN_BYTES>>>(out_w, out_b, out);
}

// round 12
// speedup vs baseline: 1.0960x; 1.0960x over previous
#include <cuda_runtime.h>
#include <cuda_bf16.h>
#include <cstdint>

// ---------------------------------------------------------------------------
// GatedAttentionUnit: S=2048, B=4, E=1024, Z=128, H=2048
// R12: operands pre-split into bf16 hi/lo arrays in GLOBAL memory (producers
//      write them directly; 3 tiny convert kernels for external inputs).
//      GEMM staging = cp.async 16B copies into a 2-stage K=32 ring (73.7 KB,
//      container-proven size) overlapping the MMA of the previous chunk.
//      Removes the cvt+STS serialization that pinned tensor at ~36%.
//      Math unchanged: mma.sync bf16 split-2 (hh+hl+lh), fp32 accum.
// ---------------------------------------------------------------------------

#define S_LEN 2048
#define BSZ 4
#define EDIM 1024
#define ZDIM 128
#define HDIM 2048
#define GEMM_THREADS 512
#define SCORE_THREADS 256

// smem stage: A tile + B tile; tile = 128 rows x [hi 16w | lo 16w | pad 4]
// ROW_W = 36 (36 % 32 == 4 -> fragment LDS bank == lane -> conflict-free)
#define ROW_W 36
#define TILE_W (128 * ROW_W)            // 4608 words
#define STAGE_W (2 * TILE_W)            // 9216 words = 36864 B
#define SMEM_DYN_BYTES (2 * STAGE_W * 4) // 73728 B (R9-proven footprint)

// ---------------- scratch (device globals; allocation-free) ----------------
__device__ float d_u [(size_t)S_LEN * BSZ * HDIM];
__device__ float d_q [(size_t)BSZ * S_LEN * ZDIM];
__device__ float d_kk[(size_t)BSZ * S_LEN * ZDIM];

__device__ __nv_bfloat16 d_xh [(size_t)S_LEN * BSZ * EDIM];
__device__ __nv_bfloat16 d_xl [(size_t)S_LEN * BSZ * EDIM];
__device__ __nv_bfloat16 d_pwh[(size_t)(2 * HDIM + ZDIM) * EDIM];
__device__ __nv_bfloat16 d_pwl[(size_t)(2 * HDIM + ZDIM) * EDIM];
__device__ __nv_bfloat16 d_owh[(size_t)EDIM * HDIM];
__device__ __nv_bfloat16 d_owl[(size_t)EDIM * HDIM];
__device__ __nv_bfloat16 d_vTh[(size_t)BSZ * HDIM * S_LEN];
__device__ __nv_bfloat16 d_vTl[(size_t)BSZ * HDIM * S_LEN];
__device__ __nv_bfloat16 d_ah [(size_t)BSZ * S_LEN * S_LEN];
__device__ __nv_bfloat16 d_al [(size_t)BSZ * S_LEN * S_LEN];
__device__ __nv_bfloat16 d_gh [(size_t)S_LEN * BSZ * HDIM];
__device__ __nv_bfloat16 d_gl [(size_t)S_LEN * BSZ * HDIM];

// ---------------------------------------------------------------------------
__device__ __forceinline__ void mma16816(float* d, const uint32_t* a, const uint32_t* b) {
    asm volatile(
        "mma.sync.aligned.m16n8k16.row.col.f32.bf16.bf16.f32 "
        "{%0,%1,%2,%3}, {%4,%5,%6,%7}, {%8,%9}, {%0,%1,%2,%3};"
        : "+f"(d[0]), "+f"(d[1]), "+f"(d[2]), "+f"(d[3])
        : "r"(a[0]), "r"(a[1]), "r"(a[2]), "r"(a[3]), "r"(b[0]), "r"(b[1]));
}

__device__ __forceinline__ void split2(float v, __nv_bfloat16& h, __nv_bfloat16& l) {
    h = __float2bfloat16_rn(v);
    l = __float2bfloat16_rn(v - __bfloat162float(h));
}

// ---------------------------------------------------------------------------
// cp.async staging: one K=32 chunk of A and B tiles (hi+lo) = 2048 16B segs;
// 512 threads x 4 segs each.
// ---------------------------------------------------------------------------
__device__ __forceinline__ void stage_chunk(
    const __nv_bfloat16* __restrict__ Ahi, const __nv_bfloat16* __restrict__ Alo, int lda,
    const __nv_bfloat16* __restrict__ Bhi, const __nv_bfloat16* __restrict__ Blo, int ldb,
    int c, uint32_t sbase)
{
    const int tid = threadIdx.x;
#pragma unroll
    for (int u = 0; u < 4; ++u) {
        int seg  = u * GEMM_THREADS + tid;
        int tile = seg >> 10;          // 0 = A, 1 = B
        int s10  = seg & 1023;
        int row  = s10 >> 3;
        int part = s10 & 7;            // 0-3 hi, 4-7 lo
        int p4   = part & 3;
        const __nv_bfloat16* gb;
        int ld;
        if (tile == 0) { gb = (part < 4) ? Ahi : Alo; ld = lda; }
        else           { gb = (part < 4) ? Bhi : Blo; ld = ldb; }
        const void* g = gb + (size_t)row * ld + c * 32 + p4 * 8;
        uint32_t sa = sbase + ((uint32_t)(tile * TILE_W + row * ROW_W
                     + ((part < 4) ? p4 * 4 : 16 + p4 * 4)) << 2);
        asm volatile("cp.async.cg.shared.global [%0], [%1], 16;" :: "r"(sa), "l"(g));
    }
}

// ---------------------------------------------------------------------------
// Core GEMM: acc(128x128) = A(128xK) * B(128xK)^T from pre-split bf16 hi/lo.
// 16 warps as 4(M) x 4(N); per-warp 32x32 via 2x4 m16n8k16 tiles.
// Split-2 via fragment reuse: bh,bl,A-hi -> hh,hl; A-lo -> lh.
// 2-stage cp.async pipeline; nChunks counts K=32 chunks.
// ---------------------------------------------------------------------------
extern __shared__ uint32_t smw[];

__device__ __forceinline__ void mma_gemm(
    const __nv_bfloat16* __restrict__ Ahi, const __nv_bfloat16* __restrict__ Alo, int lda,
    const __nv_bfloat16* __restrict__ Bhi, const __nv_bfloat16* __restrict__ Blo, int ldb,
    int nChunks, float acc[2][4][4])
{
    const int tid = threadIdx.x;
    const int lane = tid & 31, wid = tid >> 5;
    const int g = lane >> 2, tg = lane & 3;
    const int wm = wid & 3, wn = wid >> 2;
    const int arow = wm * 32 + g;
    const int brow = wn * 32 + g;
    uint32_t sb = (uint32_t)__cvta_generic_to_shared(smw);

    stage_chunk(Ahi, Alo, lda, Bhi, Blo, ldb, 0, sb);
    asm volatile("cp.async.commit_group;" ::: "memory");

    for (int c = 0; c < nChunks; ++c) {
        if (c + 1 < nChunks)
            stage_chunk(Ahi, Alo, lda, Bhi, Blo, ldb, c + 1,
                        sb + (uint32_t)(((c + 1) & 1) * (STAGE_W * 4)));
        asm volatile("cp.async.commit_group;" ::: "memory");
        asm volatile("cp.async.wait_group 1;" ::: "memory");
        __syncthreads();                       // stage c visible to all warps

        const uint32_t* Aw = smw + (c & 1) * STAGE_W;
        const uint32_t* Bw = Aw + TILE_W;
#pragma unroll 1
        for (int ks = 0; ks < 2; ++ks) {
            uint32_t bh[4][2], bl[4][2], av[2][4];
#pragma unroll
            for (int ni = 0; ni < 4; ++ni) {
                const uint32_t* pB = Bw + (brow + ni * 8) * ROW_W + ks * 8 + tg;
                bh[ni][0] = pB[0];
                bh[ni][1] = pB[4];
                bl[ni][0] = pB[16];
                bl[ni][1] = pB[20];
            }
#pragma unroll
            for (int mi = 0; mi < 2; ++mi) {
                const uint32_t* pA = Aw + (arow + mi * 16) * ROW_W + ks * 8 + tg;
                av[mi][0] = pA[0];
                av[mi][1] = pA[8 * ROW_W];
                av[mi][2] = pA[4];
                av[mi][3] = pA[8 * ROW_W + 4];
            }
#pragma unroll
            for (int mi = 0; mi < 2; ++mi)
#pragma unroll
                for (int ni = 0; ni < 4; ++ni)
                    mma16816(acc[mi][ni], av[mi], bh[ni]);
#pragma unroll
            for (int mi = 0; mi < 2; ++mi)
#pragma unroll
                for (int ni = 0; ni < 4; ++ni)
                    mma16816(acc[mi][ni], av[mi], bl[ni]);
#pragma unroll
            for (int mi = 0; mi < 2; ++mi) {
                const uint32_t* pA = Aw + (arow + mi * 16) * ROW_W + 16 + ks * 8 + tg;
                av[mi][0] = pA[0];
                av[mi][1] = pA[8 * ROW_W];
                av[mi][2] = pA[4];
                av[mi][3] = pA[8 * ROW_W + 4];
            }
#pragma unroll
            for (int mi = 0; mi < 2; ++mi)
#pragma unroll
                for (int ni = 0; ni < 4; ++ni)
                    mma16816(acc[mi][ni], av[mi], bh[ni]);
        }
        __syncthreads();                       // MMA reads done before overwrite
    }
}

__device__ __forceinline__ float silu(float v) { return v / (1.0f + __expf(-v)); }

// Per-thread element coordinates inside the 128x128 tile:
//   r = wm*32 + mi*16 + g + (e>=2 ? 8 : 0)
//   c = wn*32 + ni*8 + tg*2 + (e&1)

// ---------------------------------------------------------------------------
// K0: elementwise fp32 -> bf16 hi/lo split (for x, proj_w, out_w)
// ---------------------------------------------------------------------------
__global__ void k_split(const float* __restrict__ src,
                        __nv_bfloat16* __restrict__ hi,
                        __nv_bfloat16* __restrict__ lo, int n)
{
    int i = (blockIdx.x * blockDim.x + threadIdx.x) * 4;
    if (i < n) {
        float4 f = *(const float4*)(src + i);
        __nv_bfloat16 h[4], l[4];
        split2(f.x, h[0], l[0]); split2(f.y, h[1], l[1]);
        split2(f.z, h[2], l[2]); split2(f.w, h[3], l[3]);
        *(uint2*)(hi + i) = *(const uint2*)h;
        *(uint2*)(lo + i) = *(const uint2*)l;
    }
}

// ---------------------------------------------------------------------------
// K1: proj = silu(x @ Wp^T + bp); split into u / vT(hi,lo) / q,k
// ---------------------------------------------------------------------------
__global__ void __launch_bounds__(GEMM_THREADS, 1)
k_proj_t(const float* __restrict__ pb, const float* __restrict__ gamma,
         const float* __restrict__ beta)
{
    const int bx = blockIdx.x, by = blockIdx.y;
    float acc[2][4][4] = {};
    mma_gemm(d_xh + (size_t)by * 128 * EDIM, d_xl + (size_t)by * 128 * EDIM, EDIM,
             d_pwh + (size_t)bx * 128 * EDIM, d_pwl + (size_t)bx * 128 * EDIM, EDIM,
             EDIM / 32, acc);

    const int lane = threadIdx.x & 31, wid = threadIdx.x >> 5;
    const int g = lane >> 2, tg = lane & 3;
    const int wm = wid & 3, wn = wid >> 2;
#pragma unroll
    for (int mi = 0; mi < 2; ++mi) {
#pragma unroll
        for (int ni = 0; ni < 4; ++ni) {
#pragma unroll
            for (int e = 0; e < 4; ++e) {
                int r = by * 128 + wm * 32 + mi * 16 + g + ((e >> 1) ? 8 : 0);
                int cg = bx * 128 + wn * 32 + ni * 8 + tg * 2 + (e & 1);
                float v = silu(acc[mi][ni][e] + pb[cg]);
                int s = r >> 2, b = r & 3;
                if (bx < 16) {
                    d_u[(size_t)r * HDIM + cg] = v;
                } else if (bx < 32) {
                    int h = cg - HDIM;
                    size_t vi = ((size_t)b * HDIM + h) * S_LEN + s;
                    __nv_bfloat16 vh, vl;
                    split2(v, vh, vl);
                    d_vTh[vi] = vh;
                    d_vTl[vi] = vl;
                } else {
                    int zi = cg - 2 * HDIM;
                    size_t qi = ((size_t)b * S_LEN + s) * ZDIM + zi;
                    d_q[qi]  = v * gamma[zi]        + beta[zi];
                    d_kk[qi] = v * gamma[ZDIM + zi] + beta[ZDIM + zi];
                }
            }
        }
    }
}

// ---------------------------------------------------------------------------
// K2: scores = relu(q k^T / S + bias)^2, causal -> attn hi/lo (fp32 FFMA)
// ---------------------------------------------------------------------------
#define BK 16
__global__ void __launch_bounds__(SCORE_THREADS, 2)
k_score(const float* __restrict__ rpb)
{
    const int by = blockIdx.y, bx = blockIdx.x, b = blockIdx.z;
    if (bx > by) return;
    __shared__ float As[BK][129];
    __shared__ float Bs[BK][129];
    float acc[8][8] = {};
    const float* Ag0 = d_q  + ((size_t)b * S_LEN + by * 128) * ZDIM;
    const float* Bg0 = d_kk + ((size_t)b * S_LEN + bx * 128) * ZDIM;
    const int tid = threadIdx.x;
    const int lr = tid >> 2, lc = (tid & 3) << 2;
    const float* Ag = Ag0 + lr * ZDIM + lc;
    const float* Bg = Bg0 + lr * ZDIM + lc;
    const int ty = tid >> 4, tx = tid & 15;
    for (int kk = 0; kk < ZDIM / BK; ++kk) {
        float4 a0 = *(const float4*)(Ag);
        float4 a1 = *(const float4*)(Ag + 64 * ZDIM);
        float4 b0 = *(const float4*)(Bg);
        float4 b1 = *(const float4*)(Bg + 64 * ZDIM);
        __syncthreads();
        As[lc + 0][lr] = a0.x; As[lc + 1][lr] = a0.y; As[lc + 2][lr] = a0.z; As[lc + 3][lr] = a0.w;
        As[lc + 0][lr + 64] = a1.x; As[lc + 1][lr + 64] = a1.y; As[lc + 2][lr + 64] = a1.z; As[lc + 3][lr + 64] = a1.w;
        Bs[lc + 0][lr] = b0.x; Bs[lc + 1][lr] = b0.y; Bs[lc + 2][lr] = b0.z; Bs[lc + 3][lr] = b0.w;
        Bs[lc + 0][lr + 64] = b1.x; Bs[lc + 1][lr + 64] = b1.y; Bs[lc + 2][lr + 64] = b1.z; Bs[lc + 3][lr + 64] = b1.w;
        __syncthreads();
#pragma unroll
        for (int k = 0; k < BK; ++k) {
            float ar[8], br[8];
#pragma unroll
            for (int i = 0; i < 8; ++i) ar[i] = As[k][i * 16 + ty];
#pragma unroll
            for (int j = 0; j < 8; ++j) br[j] = Bs[k][j * 16 + tx];
#pragma unroll
            for (int i = 0; i < 8; ++i)
#pragma unroll
                for (int j = 0; j < 8; ++j) acc[i][j] += ar[i] * br[j];
        }
        Ag += BK; Bg += BK;
    }
#pragma unroll
    for (int i = 0; i < 8; ++i) {
#pragma unroll
        for (int j = 0; j < 8; ++j) {
            int r = by * 128 + i * 16 + ty;
            int c = bx * 128 + j * 16 + tx;
            float v = acc[i][j] * (1.0f / (float)S_LEN) + rpb[(S_LEN - 1) + c - r];
            float a = (c > r) ? 0.0f : fmaxf(v, 0.0f);
            float a2 = a * a;
            size_t idx = ((size_t)b * S_LEN + r) * S_LEN + c;
            __nv_bfloat16 h, l;
            split2(a2, h, l);
            d_ah[idx] = h;
            d_al[idx] = l;
        }
    }
}

// ---------------------------------------------------------------------------
// K3: g = (attn @ v) * u  (K truncated at diagonal) -> g hi/lo
// ---------------------------------------------------------------------------
__global__ void __launch_bounds__(GEMM_THREADS, 1)
k_av_t()
{
    const int bx = blockIdx.x, by = blockIdx.y, b = blockIdx.z;
    float acc[2][4][4] = {};
    mma_gemm(d_ah + ((size_t)b * S_LEN + by * 128) * S_LEN,
             d_al + ((size_t)b * S_LEN + by * 128) * S_LEN, S_LEN,
             d_vTh + ((size_t)b * HDIM + bx * 128) * S_LEN,
             d_vTl + ((size_t)b * HDIM + bx * 128) * S_LEN, S_LEN,
             (by + 1) * 4, acc);

    const int lane = threadIdx.x & 31, wid = threadIdx.x >> 5;
    const int g = lane >> 2, tg = lane & 3;
    const int wm = wid & 3, wn = wid >> 2;
#pragma unroll
    for (int mi = 0; mi < 2; ++mi) {
#pragma unroll
        for (int ni = 0; ni < 4; ++ni) {
#pragma unroll
            for (int e = 0; e < 4; ++e) {
                int q = by * 128 + wm * 32 + mi * 16 + g + ((e >> 1) ? 8 : 0);
                int h = bx * 128 + wn * 32 + ni * 8 + tg * 2 + (e & 1);
                size_t idx = ((size_t)q * BSZ + b) * HDIM + h;
                float gv = acc[mi][ni][e] * d_u[idx];
                __nv_bfloat16 gh, gl;
                split2(gv, gh, gl);
                d_gh[idx] = gh;
                d_gl[idx] = gl;
            }
        }
    }
}

// ---------------------------------------------------------------------------
// K4: out = g @ Wo^T + bo
// ---------------------------------------------------------------------------
__global__ void __launch_bounds__(GEMM_THREADS, 1)
k_out_t(const float* __restrict__ ob, float* __restrict__ out)
{
    const int bx = blockIdx.x, by = blockIdx.y;
    float acc[2][4][4] = {};
    mma_gemm(d_gh + (size_t)by * 128 * HDIM, d_gl + (size_t)by * 128 * HDIM, HDIM,
             d_owh + (size_t)bx * 128 * HDIM, d_owl + (size_t)bx * 128 * HDIM, HDIM,
             HDIM / 32, acc);

    const int lane = threadIdx.x & 31, wid = threadIdx.x >> 5;
    const int g = lane >> 2, tg = lane & 3;
    const int wm = wid & 3, wn = wid >> 2;
#pragma unroll
    for (int mi = 0; mi < 2; ++mi) {
#pragma unroll
        for (int ni = 0; ni < 4; ++ni) {
#pragma unroll
            for (int e = 0; e < 4; ++e) {
                int r = by * 128 + wm * 32 + mi * 16 + g + ((e >> 1) ? 8 : 0);
                int c = bx * 128 + wn * 32 + ni * 8 + tg * 2 + (e & 1);
                out[(size_t)r * EDIM + c] = acc[mi][ni][e] + ob[c];
            }
        }
    }
}

// ---------------------------------------------------------------------------
extern "C" void kernel_launch(void* const* d_in, const int* in_sizes, int n_in,
                              void* d_out, int out_size)
{
    const float* x      = (const float*)d_in[0];
    const float* proj_w = (const float*)d_in[2];
    const float* proj_b = (const float*)d_in[3];
    const float* out_w  = (const float*)d_in[4];
    const float* out_b  = (const float*)d_in[5];
    const float* gamma  = (const float*)d_in[6];
    const float* beta   = (const float*)d_in[7];
    const float* rpb    = (const float*)d_in[8];
    float* out = (float*)d_out;

    cudaFuncSetAttribute(k_proj_t, cudaFuncAttributeMaxDynamicSharedMemorySize, SMEM_DYN_BYTES);
    cudaFuncSetAttribute(k_av_t,   cudaFuncAttributeMaxDynamicSharedMemorySize, SMEM_DYN_BYTES);
    cudaFuncSetAttribute(k_out_t,  cudaFuncAttributeMaxDynamicSharedMemorySize, SMEM_DYN_BYTES);

    // resolve device-global scratch addresses (host side; graph-capturable)
    __nv_bfloat16 *xh, *xl, *pwh, *pwl, *owh, *owl;
    cudaGetSymbolAddress((void**)&xh,  d_xh);
    cudaGetSymbolAddress((void**)&xl,  d_xl);
    cudaGetSymbolAddress((void**)&pwh, d_pwh);
    cudaGetSymbolAddress((void**)&pwl, d_pwl);
    cudaGetSymbolAddress((void**)&owh, d_owh);
    cudaGetSymbolAddress((void**)&owl, d_owl);

    const int nx = S_LEN * BSZ * EDIM;              // 8388608
    const int npw = (2 * HDIM + ZDIM) * EDIM;       // 4325376
    const int now = EDIM * HDIM;                    // 2097152
    k_split<<<nx  / 1024, 256>>>(x,      xh,  xl,  nx);
    k_split<<<npw / 1024, 256>>>(proj_w, pwh, pwl, npw);
    k_split<<<now / 1024, 256>>>(out_w,  owh, owl, now);

    k_proj_t<<<dim3(33, 64), dim3(GEMM_THREADS), SMEM_DYN_BYTES>>>(proj_b, gamma, beta);
    k_score <<<dim3(16, 16, 4), dim3(SCORE_THREADS)>>>(rpb);
    k_av_t  <<<dim3(16, 16, 4), dim3(GEMM_THREADS), SMEM_DYN_BYTES>>>();
    k_out_t <<<dim3(8, 64), dim3(GEMM_THREADS), SMEM_DYN_BYTES>>>(out_b, out);
}

// round 13
// speedup vs baseline: 1.2502x; 1.1407x over previous
#include <cuda_runtime.h>
#include <cuda_bf16.h>
#include <cstdint>

// ---------------------------------------------------------------------------
// GatedAttentionUnit: S=2048, B=4, E=1024, Z=128, H=2048
// R13: R12 pipeline (pre-split bf16 hi/lo in global + cp.async 2-stage K=32
//      ring, 73.7 KB) but 256-thread CTAs with __launch_bounds__(256,2):
//      2 CTAs/SM = two independent barrier domains, so one CTA's MMAs cover
//      the other's staging syncs. Warp grid 2x4, per-warp 64x32 (R10 map).
//      Math unchanged: mma.sync bf16 split-2 (hh+hl+lh), fp32 accum.
// ---------------------------------------------------------------------------

#define S_LEN 2048
#define BSZ 4
#define EDIM 1024
#define ZDIM 128
#define HDIM 2048
#define GEMM_THREADS 256
#define SCORE_THREADS 256

// smem stage: A tile + B tile; tile = 128 rows x [hi 16w | lo 16w | pad 4]
// ROW_W = 36 (36 % 32 == 4 -> fragment LDS bank == lane -> conflict-free;
//             144B rows keep 16B cp.async alignment)
#define ROW_W 36
#define TILE_W (128 * ROW_W)             // 4608 words
#define STAGE_W (2 * TILE_W)             // 9216 words = 36864 B
#define SMEM_DYN_BYTES (2 * STAGE_W * 4) // 73728 B per CTA (container-proven)

// ---------------- scratch (device globals; allocation-free) ----------------
__device__ float d_u [(size_t)S_LEN * BSZ * HDIM];
__device__ float d_q [(size_t)BSZ * S_LEN * ZDIM];
__device__ float d_kk[(size_t)BSZ * S_LEN * ZDIM];

__device__ __nv_bfloat16 d_xh [(size_t)S_LEN * BSZ * EDIM];
__device__ __nv_bfloat16 d_xl [(size_t)S_LEN * BSZ * EDIM];
__device__ __nv_bfloat16 d_pwh[(size_t)(2 * HDIM + ZDIM) * EDIM];
__device__ __nv_bfloat16 d_pwl[(size_t)(2 * HDIM + ZDIM) * EDIM];
__device__ __nv_bfloat16 d_owh[(size_t)EDIM * HDIM];
__device__ __nv_bfloat16 d_owl[(size_t)EDIM * HDIM];
__device__ __nv_bfloat16 d_vTh[(size_t)BSZ * HDIM * S_LEN];
__device__ __nv_bfloat16 d_vTl[(size_t)BSZ * HDIM * S_LEN];
__device__ __nv_bfloat16 d_ah [(size_t)BSZ * S_LEN * S_LEN];
__device__ __nv_bfloat16 d_al [(size_t)BSZ * S_LEN * S_LEN];
__device__ __nv_bfloat16 d_gh [(size_t)S_LEN * BSZ * HDIM];
__device__ __nv_bfloat16 d_gl [(size_t)S_LEN * BSZ * HDIM];

// ---------------------------------------------------------------------------
__device__ __forceinline__ void mma16816(float* d, const uint32_t* a, const uint32_t* b) {
    asm volatile(
        "mma.sync.aligned.m16n8k16.row.col.f32.bf16.bf16.f32 "
        "{%0,%1,%2,%3}, {%4,%5,%6,%7}, {%8,%9}, {%0,%1,%2,%3};"
        : "+f"(d[0]), "+f"(d[1]), "+f"(d[2]), "+f"(d[3])
        : "r"(a[0]), "r"(a[1]), "r"(a[2]), "r"(a[3]), "r"(b[0]), "r"(b[1]));
}

__device__ __forceinline__ void split2(float v, __nv_bfloat16& h, __nv_bfloat16& l) {
    h = __float2bfloat16_rn(v);
    l = __float2bfloat16_rn(v - __bfloat162float(h));
}

// ---------------------------------------------------------------------------
// cp.async staging: one K=32 chunk of A and B tiles (hi+lo) = 2048 16B segs;
// 256 threads x 8 segs each.
// ---------------------------------------------------------------------------
__device__ __forceinline__ void stage_chunk(
    const __nv_bfloat16* __restrict__ Ahi, const __nv_bfloat16* __restrict__ Alo, int lda,
    const __nv_bfloat16* __restrict__ Bhi, const __nv_bfloat16* __restrict__ Blo, int ldb,
    int c, uint32_t sbase)
{
    const int tid = threadIdx.x;
#pragma unroll
    for (int u = 0; u < 8; ++u) {
        int seg  = u * GEMM_THREADS + tid;
        int tile = seg >> 10;          // 0 = A, 1 = B
        int s10  = seg & 1023;
        int row  = s10 >> 3;
        int part = s10 & 7;            // 0-3 hi, 4-7 lo
        int p4   = part & 3;
        const __nv_bfloat16* gb;
        int ld;
        if (tile == 0) { gb = (part < 4) ? Ahi : Alo; ld = lda; }
        else           { gb = (part < 4) ? Bhi : Blo; ld = ldb; }
        const void* g = gb + (size_t)row * ld + c * 32 + p4 * 8;
        uint32_t sa = sbase + ((uint32_t)(tile * TILE_W + row * ROW_W
                     + ((part < 4) ? p4 * 4 : 16 + p4 * 4)) << 2);
        asm volatile("cp.async.cg.shared.global [%0], [%1], 16;" :: "r"(sa), "l"(g));
    }
}

// ---------------------------------------------------------------------------
// Core GEMM: acc(128x128) = A(128xK) * B(128xK)^T from pre-split bf16 hi/lo.
// 8 warps as 2(M) x 4(N); per-warp 64x32 via 4x4 m16n8k16 tiles.
// Split-2 via fragment reuse: bh,bl,A-hi -> hh,hl; A-lo -> lh.
// 2-stage cp.async pipeline; nChunks counts K=32 chunks.
// ---------------------------------------------------------------------------
extern __shared__ uint32_t smw[];

__device__ __forceinline__ void mma_gemm(
    const __nv_bfloat16* __restrict__ Ahi, const __nv_bfloat16* __restrict__ Alo, int lda,
    const __nv_bfloat16* __restrict__ Bhi, const __nv_bfloat16* __restrict__ Blo, int ldb,
    int nChunks, float acc[4][4][4])
{
    const int tid = threadIdx.x;
    const int lane = tid & 31, wid = tid >> 5;
    const int g = lane >> 2, tg = lane & 3;
    const int wm = wid & 1, wn = wid >> 1;
    const int arow = wm * 64 + g;
    const int brow = wn * 32 + g;
    uint32_t sb = (uint32_t)__cvta_generic_to_shared(smw);

    stage_chunk(Ahi, Alo, lda, Bhi, Blo, ldb, 0, sb);
    asm volatile("cp.async.commit_group;" ::: "memory");

    for (int c = 0; c < nChunks; ++c) {
        if (c + 1 < nChunks)
            stage_chunk(Ahi, Alo, lda, Bhi, Blo, ldb, c + 1,
                        sb + (uint32_t)(((c + 1) & 1) * (STAGE_W * 4)));
        asm volatile("cp.async.commit_group;" ::: "memory");
        asm volatile("cp.async.wait_group 1;" ::: "memory");
        __syncthreads();                       // stage c visible to all warps

        const uint32_t* Aw = smw + (c & 1) * STAGE_W;
        const uint32_t* Bw = Aw + TILE_W;
#pragma unroll 1
        for (int ks = 0; ks < 2; ++ks) {
            uint32_t bh[4][2], bl[4][2], av[4][4];
#pragma unroll
            for (int ni = 0; ni < 4; ++ni) {
                const uint32_t* pB = Bw + (brow + ni * 8) * ROW_W + ks * 8 + tg;
                bh[ni][0] = pB[0];
                bh[ni][1] = pB[4];
                bl[ni][0] = pB[16];
                bl[ni][1] = pB[20];
            }
#pragma unroll
            for (int mi = 0; mi < 4; ++mi) {
                const uint32_t* pA = Aw + (arow + mi * 16) * ROW_W + ks * 8 + tg;
                av[mi][0] = pA[0];
                av[mi][1] = pA[8 * ROW_W];
                av[mi][2] = pA[4];
                av[mi][3] = pA[8 * ROW_W + 4];
            }
#pragma unroll
            for (int mi = 0; mi < 4; ++mi)
#pragma unroll
                for (int ni = 0; ni < 4; ++ni)
                    mma16816(acc[mi][ni], av[mi], bh[ni]);
#pragma unroll
            for (int mi = 0; mi < 4; ++mi)
#pragma unroll
                for (int ni = 0; ni < 4; ++ni)
                    mma16816(acc[mi][ni], av[mi], bl[ni]);
#pragma unroll
            for (int mi = 0; mi < 4; ++mi) {
                const uint32_t* pA = Aw + (arow + mi * 16) * ROW_W + 16 + ks * 8 + tg;
                av[mi][0] = pA[0];
                av[mi][1] = pA[8 * ROW_W];
                av[mi][2] = pA[4];
                av[mi][3] = pA[8 * ROW_W + 4];
            }
#pragma unroll
            for (int mi = 0; mi < 4; ++mi)
#pragma unroll
                for (int ni = 0; ni < 4; ++ni)
                    mma16816(acc[mi][ni], av[mi], bh[ni]);
        }
        __syncthreads();                       // MMA reads done before overwrite
    }
}

__device__ __forceinline__ float silu(float v) { return v / (1.0f + __expf(-v)); }

// Per-thread element coordinates inside the 128x128 tile:
//   r = wm*64 + mi*16 + g + (e>=2 ? 8 : 0)
//   c = wn*32 + ni*8 + tg*2 + (e&1)

// ---------------------------------------------------------------------------
// K0: elementwise fp32 -> bf16 hi/lo split (for x, proj_w, out_w)
// ---------------------------------------------------------------------------
__global__ void k_split(const float* __restrict__ src,
                        __nv_bfloat16* __restrict__ hi,
                        __nv_bfloat16* __restrict__ lo, int n)
{
    int i = (blockIdx.x * blockDim.x + threadIdx.x) * 4;
    if (i < n) {
        float4 f = *(const float4*)(src + i);
        __nv_bfloat16 h[4], l[4];
        split2(f.x, h[0], l[0]); split2(f.y, h[1], l[1]);
        split2(f.z, h[2], l[2]); split2(f.w, h[3], l[3]);
        *(uint2*)(hi + i) = *(const uint2*)h;
        *(uint2*)(lo + i) = *(const uint2*)l;
    }
}

// ---------------------------------------------------------------------------
// K1: proj = silu(x @ Wp^T + bp); split into u / vT(hi,lo) / q,k
// ---------------------------------------------------------------------------
__global__ void __launch_bounds__(GEMM_THREADS, 2)
k_proj_t(const float* __restrict__ pb, const float* __restrict__ gamma,
         const float* __restrict__ beta)
{
    const int bx = blockIdx.x, by = blockIdx.y;
    float acc[4][4][4] = {};
    mma_gemm(d_xh + (size_t)by * 128 * EDIM, d_xl + (size_t)by * 128 * EDIM, EDIM,
             d_pwh + (size_t)bx * 128 * EDIM, d_pwl + (size_t)bx * 128 * EDIM, EDIM,
             EDIM / 32, acc);

    const int lane = threadIdx.x & 31, wid = threadIdx.x >> 5;
    const int g = lane >> 2, tg = lane & 3;
    const int wm = wid & 1, wn = wid >> 1;
#pragma unroll
    for (int mi = 0; mi < 4; ++mi) {
#pragma unroll
        for (int ni = 0; ni < 4; ++ni) {
#pragma unroll
            for (int e = 0; e < 4; ++e) {
                int r = by * 128 + wm * 64 + mi * 16 + g + ((e >> 1) ? 8 : 0);
                int cg = bx * 128 + wn * 32 + ni * 8 + tg * 2 + (e & 1);
                float v = silu(acc[mi][ni][e] + pb[cg]);
                int s = r >> 2, b = r & 3;
                if (bx < 16) {
                    d_u[(size_t)r * HDIM + cg] = v;
                } else if (bx < 32) {
                    int h = cg - HDIM;
                    size_t vi = ((size_t)b * HDIM + h) * S_LEN + s;
                    __nv_bfloat16 vh, vl;
                    split2(v, vh, vl);
                    d_vTh[vi] = vh;
                    d_vTl[vi] = vl;
                } else {
                    int zi = cg - 2 * HDIM;
                    size_t qi = ((size_t)b * S_LEN + s) * ZDIM + zi;
                    d_q[qi]  = v * gamma[zi]        + beta[zi];
                    d_kk[qi] = v * gamma[ZDIM + zi] + beta[ZDIM + zi];
                }
            }
        }
    }
}

// ---------------------------------------------------------------------------
// K2: scores = relu(q k^T / S + bias)^2, causal -> attn hi/lo (fp32 FFMA)
// ---------------------------------------------------------------------------
#define BK 16
__global__ void __launch_bounds__(SCORE_THREADS, 2)
k_score(const float* __restrict__ rpb)
{
    const int by = blockIdx.y, bx = blockIdx.x, b = blockIdx.z;
    if (bx > by) return;
    __shared__ float As[BK][129];
    __shared__ float Bs[BK][129];
    float acc[8][8] = {};
    const float* Ag0 = d_q  + ((size_t)b * S_LEN + by * 128) * ZDIM;
    const float* Bg0 = d_kk + ((size_t)b * S_LEN + bx * 128) * ZDIM;
    const int tid = threadIdx.x;
    const int lr = tid >> 2, lc = (tid & 3) << 2;
    const float* Ag = Ag0 + lr * ZDIM + lc;
    const float* Bg = Bg0 + lr * ZDIM + lc;
    const int ty = tid >> 4, tx = tid & 15;
    for (int kk = 0; kk < ZDIM / BK; ++kk) {
        float4 a0 = *(const float4*)(Ag);
        float4 a1 = *(const float4*)(Ag + 64 * ZDIM);
        float4 b0 = *(const float4*)(Bg);
        float4 b1 = *(const float4*)(Bg + 64 * ZDIM);
        __syncthreads();
        As[lc + 0][lr] = a0.x; As[lc + 1][lr] = a0.y; As[lc + 2][lr] = a0.z; As[lc + 3][lr] = a0.w;
        As[lc + 0][lr + 64] = a1.x; As[lc + 1][lr + 64] = a1.y; As[lc + 2][lr + 64] = a1.z; As[lc + 3][lr + 64] = a1.w;
        Bs[lc + 0][lr] = b0.x; Bs[lc + 1][lr] = b0.y; Bs[lc + 2][lr] = b0.z; Bs[lc + 3][lr] = b0.w;
        Bs[lc + 0][lr + 64] = b1.x; Bs[lc + 1][lr + 64] = b1.y; Bs[lc + 2][lr + 64] = b1.z; Bs[lc + 3][lr + 64] = b1.w;
        __syncthreads();
#pragma unroll
        for (int k = 0; k < BK; ++k) {
            float ar[8], br[8];
#pragma unroll
            for (int i = 0; i < 8; ++i) ar[i] = As[k][i * 16 + ty];
#pragma unroll
            for (int j = 0; j < 8; ++j) br[j] = Bs[k][j * 16 + tx];
#pragma unroll
            for (int i = 0; i < 8; ++i)
#pragma unroll
                for (int j = 0; j < 8; ++j) acc[i][j] += ar[i] * br[j];
        }
        Ag += BK; Bg += BK;
    }
#pragma unroll
    for (int i = 0; i < 8; ++i) {
#pragma unroll
        for (int j = 0; j < 8; ++j) {
            int r = by * 128 + i * 16 + ty;
            int c = bx * 128 + j * 16 + tx;
            float v = acc[i][j] * (1.0f / (float)S_LEN) + rpb[(S_LEN - 1) + c - r];
            float a = (c > r) ? 0.0f : fmaxf(v, 0.0f);
            float a2 = a * a;
            size_t idx = ((size_t)b * S_LEN + r) * S_LEN + c;
            __nv_bfloat16 h, l;
            split2(a2, h, l);
            d_ah[idx] = h;
            d_al[idx] = l;
        }
    }
}

// ---------------------------------------------------------------------------
// K3: g = (attn @ v) * u  (K truncated at diagonal) -> g hi/lo
// ---------------------------------------------------------------------------
__global__ void __launch_bounds__(GEMM_THREADS, 2)
k_av_t()
{
    const int bx = blockIdx.x, by = blockIdx.y, b = blockIdx.z;
    float acc[4][4][4] = {};
    mma_gemm(d_ah + ((size_t)b * S_LEN + by * 128) * S_LEN,
             d_al + ((size_t)b * S_LEN + by * 128) * S_LEN, S_LEN,
             d_vTh + ((size_t)b * HDIM + bx * 128) * S_LEN,
             d_vTl + ((size_t)b * HDIM + bx * 128) * S_LEN, S_LEN,
             (by + 1) * 4, acc);

    const int lane = threadIdx.x & 31, wid = threadIdx.x >> 5;
    const int g = lane >> 2, tg = lane & 3;
    const int wm = wid & 1, wn = wid >> 1;
#pragma unroll
    for (int mi = 0; mi < 4; ++mi) {
#pragma unroll
        for (int ni = 0; ni < 4; ++ni) {
#pragma unroll
            for (int e = 0; e < 4; ++e) {
                int q = by * 128 + wm * 64 + mi * 16 + g + ((e >> 1) ? 8 : 0);
                int h = bx * 128 + wn * 32 + ni * 8 + tg * 2 + (e & 1);
                size_t idx = ((size_t)q * BSZ + b) * HDIM + h;
                float gv = acc[mi][ni][e] * d_u[idx];
                __nv_bfloat16 gh, gl;
                split2(gv, gh, gl);
                d_gh[idx] = gh;
                d_gl[idx] = gl;
            }
        }
    }
}

// ---------------------------------------------------------------------------
// K4: out = g @ Wo^T + bo
// ---------------------------------------------------------------------------
__global__ void __launch_bounds__(GEMM_THREADS, 2)
k_out_t(const float* __restrict__ ob, float* __restrict__ out)
{
    const int bx = blockIdx.x, by = blockIdx.y;
    float acc[4][4][4] = {};
    mma_gemm(d_gh + (size_t)by * 128 * HDIM, d_gl + (size_t)by * 128 * HDIM, HDIM,
             d_owh + (size_t)bx * 128 * HDIM, d_owl + (size_t)bx * 128 * HDIM, HDIM,
             HDIM / 32, acc);

    const int lane = threadIdx.x & 31, wid = threadIdx.x >> 5;
    const int g = lane >> 2, tg = lane & 3;
    const int wm = wid & 1, wn = wid >> 1;
#pragma unroll
    for (int mi = 0; mi < 4; ++mi) {
#pragma unroll
        for (int ni = 0; ni < 4; ++ni) {
#pragma unroll
            for (int e = 0; e < 4; ++e) {
                int r = by * 128 + wm * 64 + mi * 16 + g + ((e >> 1) ? 8 : 0);
                int c = bx * 128 + wn * 32 + ni * 8 + tg * 2 + (e & 1);
                out[(size_t)r * EDIM + c] = acc[mi][ni][e] + ob[c];
            }
        }
    }
}

// ---------------------------------------------------------------------------
extern "C" void kernel_launch(void* const* d_in, const int* in_sizes, int n_in,
                              void* d_out, int out_size)
{
    const float* x      = (const float*)d_in[0];
    const float* proj_w = (const float*)d_in[2];
    const float* proj_b = (const float*)d_in[3];
    const float* out_w  = (const float*)d_in[4];
    const float* out_b  = (const float*)d_in[5];
    const float* gamma  = (const float*)d_in[6];
    const float* beta   = (const float*)d_in[7];
    const float* rpb    = (const float*)d_in[8];
    float* out = (float*)d_out;

    cudaFuncSetAttribute(k_proj_t, cudaFuncAttributeMaxDynamicSharedMemorySize, SMEM_DYN_BYTES);
    cudaFuncSetAttribute(k_av_t,   cudaFuncAttributeMaxDynamicSharedMemorySize, SMEM_DYN_BYTES);
    cudaFuncSetAttribute(k_out_t,  cudaFuncAttributeMaxDynamicSharedMemorySize, SMEM_DYN_BYTES);

    __nv_bfloat16 *xh, *xl, *pwh, *pwl, *owh, *owl;
    cudaGetSymbolAddress((void**)&xh,  d_xh);
    cudaGetSymbolAddress((void**)&xl,  d_xl);
    cudaGetSymbolAddress((void**)&pwh, d_pwh);
    cudaGetSymbolAddress((void**)&pwl, d_pwl);
    cudaGetSymbolAddress((void**)&owh, d_owh);
    cudaGetSymbolAddress((void**)&owl, d_owl);

    const int nx = S_LEN * BSZ * EDIM;
    const int npw = (2 * HDIM + ZDIM) * EDIM;
    const int now = EDIM * HDIM;
    k_split<<<nx  / 1024, 256>>>(x,      xh,  xl,  nx);
    k_split<<<npw / 1024, 256>>>(proj_w, pwh, pwl, npw);
    k_split<<<now / 1024, 256>>>(out_w,  owh, owl, now);

    k_proj_t<<<dim3(33, 64), dim3(GEMM_THREADS), SMEM_DYN_BYTES>>>(proj_b, gamma, beta);
    k_score <<<dim3(16, 16, 4), dim3(SCORE_THREADS)>>>(rpb);
    k_av_t  <<<dim3(16, 16, 4), dim3(GEMM_THREADS), SMEM_DYN_BYTES>>>();
    k_out_t <<<dim3(8, 64), dim3(GEMM_THREADS), SMEM_DYN_BYTES>>>(out_b, out);
}

// round 14
// speedup vs baseline: 1.3373x; 1.0697x over previous
#include <cuda_runtime.h>
#include <cuda_bf16.h>
#include <cstdint>

// ---------------------------------------------------------------------------
// GatedAttentionUnit: S=2048, B=4, E=1024, Z=128, H=2048
// R14: R13 (pre-split bf16 hi/lo global + cp.async 2-stage K=32 ring,
//      73.7 KB, 2 CTAs/SM) with inner-loop fragment loads converted to
//      ldmatrix.m8n8.x4: 48 scalar LDS -> 12 ldmatrix per warp per ks-group.
//      Math unchanged: mma.sync bf16 split-2 (hh+hl+lh), fp32 accum.
// ---------------------------------------------------------------------------

#define S_LEN 2048
#define BSZ 4
#define EDIM 1024
#define ZDIM 128
#define HDIM 2048
#define GEMM_THREADS 256
#define SCORE_THREADS 256

// smem stage: A tile + B tile; tile = 128 rows x [hi 16w | lo 16w | pad 4]
// ROW_W = 36 words (144 B: 16B-aligned rows; banks 4r -> ldmatrix conflict-free)
#define ROW_W 36
#define TILE_W (128 * ROW_W)             // 4608 words
#define STAGE_W (2 * TILE_W)             // 9216 words = 36864 B
#define SMEM_DYN_BYTES (2 * STAGE_W * 4) // 73728 B per CTA (container-proven)

// ---------------- scratch (device globals; allocation-free) ----------------
__device__ float d_u [(size_t)S_LEN * BSZ * HDIM];
__device__ float d_q [(size_t)BSZ * S_LEN * ZDIM];
__device__ float d_kk[(size_t)BSZ * S_LEN * ZDIM];

__device__ __nv_bfloat16 d_xh [(size_t)S_LEN * BSZ * EDIM];
__device__ __nv_bfloat16 d_xl [(size_t)S_LEN * BSZ * EDIM];
__device__ __nv_bfloat16 d_pwh[(size_t)(2 * HDIM + ZDIM) * EDIM];
__device__ __nv_bfloat16 d_pwl[(size_t)(2 * HDIM + ZDIM) * EDIM];
__device__ __nv_bfloat16 d_owh[(size_t)EDIM * HDIM];
__device__ __nv_bfloat16 d_owl[(size_t)EDIM * HDIM];
__device__ __nv_bfloat16 d_vTh[(size_t)BSZ * HDIM * S_LEN];
__device__ __nv_bfloat16 d_vTl[(size_t)BSZ * HDIM * S_LEN];
__device__ __nv_bfloat16 d_ah [(size_t)BSZ * S_LEN * S_LEN];
__device__ __nv_bfloat16 d_al [(size_t)BSZ * S_LEN * S_LEN];
__device__ __nv_bfloat16 d_gh [(size_t)S_LEN * BSZ * HDIM];
__device__ __nv_bfloat16 d_gl [(size_t)S_LEN * BSZ * HDIM];

// ---------------------------------------------------------------------------
__device__ __forceinline__ void mma16816(float* d, const uint32_t* a, const uint32_t* b) {
    asm volatile(
        "mma.sync.aligned.m16n8k16.row.col.f32.bf16.bf16.f32 "
        "{%0,%1,%2,%3}, {%4,%5,%6,%7}, {%8,%9}, {%0,%1,%2,%3};"
        : "+f"(d[0]), "+f"(d[1]), "+f"(d[2]), "+f"(d[3])
        : "r"(a[0]), "r"(a[1]), "r"(a[2]), "r"(a[3]), "r"(b[0]), "r"(b[1]));
}

__device__ __forceinline__ void ldm_x4(uint32_t& r0, uint32_t& r1,
                                       uint32_t& r2, uint32_t& r3, uint32_t addr) {
    asm volatile("ldmatrix.sync.aligned.m8n8.x4.shared.b16 {%0,%1,%2,%3}, [%4];"
                 : "=r"(r0), "=r"(r1), "=r"(r2), "=r"(r3) : "r"(addr));
}

__device__ __forceinline__ void split2(float v, __nv_bfloat16& h, __nv_bfloat16& l) {
    h = __float2bfloat16_rn(v);
    l = __float2bfloat16_rn(v - __bfloat162float(h));
}

// ---------------------------------------------------------------------------
// cp.async staging: one K=32 chunk of A and B tiles (hi+lo) = 2048 16B segs;
// 256 threads x 8 segs each.
// ---------------------------------------------------------------------------
__device__ __forceinline__ void stage_chunk(
    const __nv_bfloat16* __restrict__ Ahi, const __nv_bfloat16* __restrict__ Alo, int lda,
    const __nv_bfloat16* __restrict__ Bhi, const __nv_bfloat16* __restrict__ Blo, int ldb,
    int c, uint32_t sbase)
{
    const int tid = threadIdx.x;
#pragma unroll
    for (int u = 0; u < 8; ++u) {
        int seg  = u * GEMM_THREADS + tid;
        int tile = seg >> 10;          // 0 = A, 1 = B
        int s10  = seg & 1023;
        int row  = s10 >> 3;
        int part = s10 & 7;            // 0-3 hi, 4-7 lo
        int p4   = part & 3;
        const __nv_bfloat16* gb;
        int ld;
        if (tile == 0) { gb = (part < 4) ? Ahi : Alo; ld = lda; }
        else           { gb = (part < 4) ? Bhi : Blo; ld = ldb; }
        const void* g = gb + (size_t)row * ld + c * 32 + p4 * 8;
        uint32_t sa = sbase + ((uint32_t)(tile * TILE_W + row * ROW_W
                     + ((part < 4) ? p4 * 4 : 16 + p4 * 4)) << 2);
        asm volatile("cp.async.cg.shared.global [%0], [%1], 16;" :: "r"(sa), "l"(g));
    }
}

// ---------------------------------------------------------------------------
// Core GEMM: acc(128x128) = A(128xK) * B(128xK)^T from pre-split bf16 hi/lo.
// 8 warps as 2(M) x 4(N); per-warp 64x32 via 4x4 m16n8k16 tiles.
// Fragment loads via ldmatrix.x4. Split-2: A-hi(bh,bl) then A-lo(bh).
// 2-stage cp.async pipeline; nChunks counts K=32 chunks.
// ---------------------------------------------------------------------------
extern __shared__ uint32_t smw[];

__device__ __forceinline__ void mma_gemm(
    const __nv_bfloat16* __restrict__ Ahi, const __nv_bfloat16* __restrict__ Alo, int lda,
    const __nv_bfloat16* __restrict__ Bhi, const __nv_bfloat16* __restrict__ Blo, int ldb,
    int nChunks, float acc[4][4][4])
{
    const int tid = threadIdx.x;
    const int lane = tid & 31, wid = tid >> 5;
    const int wm = wid & 1, wn = wid >> 1;
    uint32_t sb = (uint32_t)__cvta_generic_to_shared(smw);

    // per-thread ldmatrix address offsets (words), relative to tile base
    const int t8 = lane & 7, m4 = lane >> 3;         // m4 = matrix id 0..3
    // A x4: m0=(r0-7,k0-7) m1=(r8-15,k0-7) m2=(r0-7,k8-15) m3=(r8-15,k8-15)
    const int aoffw = (wm * 64 + t8 + (m4 & 1) * 8) * ROW_W + (m4 >> 1) * 4;
    // B x4: m0=(ni rows,k0-7) m1=(ni,k8-15) m2=(ni+1,k0-7) m3=(ni+1,k8-15)
    const int boffw = (wn * 32 + t8 + (m4 >> 1) * 8) * ROW_W + (m4 & 1) * 4;

    stage_chunk(Ahi, Alo, lda, Bhi, Blo, ldb, 0, sb);
    asm volatile("cp.async.commit_group;" ::: "memory");

    for (int c = 0; c < nChunks; ++c) {
        if (c + 1 < nChunks)
            stage_chunk(Ahi, Alo, lda, Bhi, Blo, ldb, c + 1,
                        sb + (uint32_t)(((c + 1) & 1) * (STAGE_W * 4)));
        asm volatile("cp.async.commit_group;" ::: "memory");
        asm volatile("cp.async.wait_group 1;" ::: "memory");
        __syncthreads();                       // stage c visible to all warps

        const uint32_t stg = sb + (uint32_t)((c & 1) * (STAGE_W * 4));
        const uint32_t aB = stg + (uint32_t)(aoffw << 2);
        const uint32_t bB = stg + (uint32_t)((TILE_W + boffw) << 2);
#pragma unroll 1
        for (int ks = 0; ks < 2; ++ks) {
            uint32_t av[4][4], bh[4][2], bl[4][2];
#pragma unroll
            for (int mi = 0; mi < 4; ++mi)     // A-hi
                ldm_x4(av[mi][0], av[mi][1], av[mi][2], av[mi][3],
                       aB + ((mi * 576 + ks * 8) << 2));
#pragma unroll
            for (int np = 0; np < 2; ++np) {   // B-hi (2 ni per ldmatrix)
                ldm_x4(bh[2 * np][0], bh[2 * np][1], bh[2 * np + 1][0], bh[2 * np + 1][1],
                       bB + ((np * 576 + ks * 8) << 2));
                ldm_x4(bl[2 * np][0], bl[2 * np][1], bl[2 * np + 1][0], bl[2 * np + 1][1],
                       bB + ((np * 576 + ks * 8 + 16) << 2));
            }
#pragma unroll
            for (int mi = 0; mi < 4; ++mi)
#pragma unroll
                for (int ni = 0; ni < 4; ++ni)
                    mma16816(acc[mi][ni], av[mi], bh[ni]);
#pragma unroll
            for (int mi = 0; mi < 4; ++mi)
#pragma unroll
                for (int ni = 0; ni < 4; ++ni)
                    mma16816(acc[mi][ni], av[mi], bl[ni]);
#pragma unroll
            for (int mi = 0; mi < 4; ++mi)     // A-lo (reuse av regs)
                ldm_x4(av[mi][0], av[mi][1], av[mi][2], av[mi][3],
                       aB + ((mi * 576 + ks * 8 + 16) << 2));
#pragma unroll
            for (int mi = 0; mi < 4; ++mi)
#pragma unroll
                for (int ni = 0; ni < 4; ++ni)
                    mma16816(acc[mi][ni], av[mi], bh[ni]);
        }
        __syncthreads();                       // MMA reads done before overwrite
    }
}

__device__ __forceinline__ float silu(float v) { return v / (1.0f + __expf(-v)); }

// Per-thread element coordinates inside the 128x128 tile:
//   r = wm*64 + mi*16 + g + (e>=2 ? 8 : 0)
//   c = wn*32 + ni*8 + tg*2 + (e&1)

// ---------------------------------------------------------------------------
// K0: elementwise fp32 -> bf16 hi/lo split (for x, proj_w, out_w)
// ---------------------------------------------------------------------------
__global__ void k_split(const float* __restrict__ src,
                        __nv_bfloat16* __restrict__ hi,
                        __nv_bfloat16* __restrict__ lo, int n)
{
    int i = (blockIdx.x * blockDim.x + threadIdx.x) * 4;
    if (i < n) {
        float4 f = *(const float4*)(src + i);
        __nv_bfloat16 h[4], l[4];
        split2(f.x, h[0], l[0]); split2(f.y, h[1], l[1]);
        split2(f.z, h[2], l[2]); split2(f.w, h[3], l[3]);
        *(uint2*)(hi + i) = *(const uint2*)h;
        *(uint2*)(lo + i) = *(const uint2*)l;
    }
}

// ---------------------------------------------------------------------------
// K1: proj = silu(x @ Wp^T + bp); split into u / vT(hi,lo) / q,k
// ---------------------------------------------------------------------------
__global__ void __launch_bounds__(GEMM_THREADS, 2)
k_proj_t(const float* __restrict__ pb, const float* __restrict__ gamma,
         const float* __restrict__ beta)
{
    const int bx = blockIdx.x, by = blockIdx.y;
    float acc[4][4][4] = {};
    mma_gemm(d_xh + (size_t)by * 128 * EDIM, d_xl + (size_t)by * 128 * EDIM, EDIM,
             d_pwh + (size_t)bx * 128 * EDIM, d_pwl + (size_t)bx * 128 * EDIM, EDIM,
             EDIM / 32, acc);

    const int lane = threadIdx.x & 31, wid = threadIdx.x >> 5;
    const int g = lane >> 2, tg = lane & 3;
    const int wm = wid & 1, wn = wid >> 1;
#pragma unroll
    for (int mi = 0; mi < 4; ++mi) {
#pragma unroll
        for (int ni = 0; ni < 4; ++ni) {
#pragma unroll
            for (int e = 0; e < 4; ++e) {
                int r = by * 128 + wm * 64 + mi * 16 + g + ((e >> 1) ? 8 : 0);
                int cg = bx * 128 + wn * 32 + ni * 8 + tg * 2 + (e & 1);
                float v = silu(acc[mi][ni][e] + pb[cg]);
                int s = r >> 2, b = r & 3;
                if (bx < 16) {
                    d_u[(size_t)r * HDIM + cg] = v;
                } else if (bx < 32) {
                    int h = cg - HDIM;
                    size_t vi = ((size_t)b * HDIM + h) * S_LEN + s;
                    __nv_bfloat16 vh, vl;
                    split2(v, vh, vl);
                    d_vTh[vi] = vh;
                    d_vTl[vi] = vl;
                } else {
                    int zi = cg - 2 * HDIM;
                    size_t qi = ((size_t)b * S_LEN + s) * ZDIM + zi;
                    d_q[qi]  = v * gamma[zi]        + beta[zi];
                    d_kk[qi] = v * gamma[ZDIM + zi] + beta[ZDIM + zi];
                }
            }
        }
    }
}

// ---------------------------------------------------------------------------
// K2: scores = relu(q k^T / S + bias)^2, causal -> attn hi/lo (fp32 FFMA)
// ---------------------------------------------------------------------------
#define BK 16
__global__ void __launch_bounds__(SCORE_THREADS, 2)
k_score(const float* __restrict__ rpb)
{
    const int by = blockIdx.y, bx = blockIdx.x, b = blockIdx.z;
    if (bx > by) return;
    __shared__ float As[BK][129];
    __shared__ float Bs[BK][129];
    float acc[8][8] = {};
    const float* Ag0 = d_q  + ((size_t)b * S_LEN + by * 128) * ZDIM;
    const float* Bg0 = d_kk + ((size_t)b * S_LEN + bx * 128) * ZDIM;
    const int tid = threadIdx.x;
    const int lr = tid >> 2, lc = (tid & 3) << 2;
    const float* Ag = Ag0 + lr * ZDIM + lc;
    const float* Bg = Bg0 + lr * ZDIM + lc;
    const int ty = tid >> 4, tx = tid & 15;
    for (int kk = 0; kk < ZDIM / BK; ++kk) {
        float4 a0 = *(const float4*)(Ag);
        float4 a1 = *(const float4*)(Ag + 64 * ZDIM);
        float4 b0 = *(const float4*)(Bg);
        float4 b1 = *(const float4*)(Bg + 64 * ZDIM);
        __syncthreads();
        As[lc + 0][lr] = a0.x; As[lc + 1][lr] = a0.y; As[lc + 2][lr] = a0.z; As[lc + 3][lr] = a0.w;
        As[lc + 0][lr + 64] = a1.x; As[lc + 1][lr + 64] = a1.y; As[lc + 2][lr + 64] = a1.z; As[lc + 3][lr + 64] = a1.w;
        Bs[lc + 0][lr] = b0.x; Bs[lc + 1][lr] = b0.y; Bs[lc + 2][lr] = b0.z; Bs[lc + 3][lr] = b0.w;
        Bs[lc + 0][lr + 64] = b1.x; Bs[lc + 1][lr + 64] = b1.y; Bs[lc + 2][lr + 64] = b1.z; Bs[lc + 3][lr + 64] = b1.w;
        __syncthreads();
#pragma unroll
        for (int k = 0; k < BK; ++k) {
            float ar[8], br[8];
#pragma unroll
            for (int i = 0; i < 8; ++i) ar[i] = As[k][i * 16 + ty];
#pragma unroll
            for (int j = 0; j < 8; ++j) br[j] = Bs[k][j * 16 + tx];
#pragma unroll
            for (int i = 0; i < 8; ++i)
#pragma unroll
                for (int j = 0; j < 8; ++j) acc[i][j] += ar[i] * br[j];
        }
        Ag += BK; Bg += BK;
    }
#pragma unroll
    for (int i = 0; i < 8; ++i) {
#pragma unroll
        for (int j = 0; j < 8; ++j) {
            int r = by * 128 + i * 16 + ty;
            int c = bx * 128 + j * 16 + tx;
            float v = acc[i][j] * (1.0f / (float)S_LEN) + rpb[(S_LEN - 1) + c - r];
            float a = (c > r) ? 0.0f : fmaxf(v, 0.0f);
            float a2 = a * a;
            size_t idx = ((size_t)b * S_LEN + r) * S_LEN + c;
            __nv_bfloat16 h, l;
            split2(a2, h, l);
            d_ah[idx] = h;
            d_al[idx] = l;
        }
    }
}

// ---------------------------------------------------------------------------
// K3: g = (attn @ v) * u  (K truncated at diagonal) -> g hi/lo
// ---------------------------------------------------------------------------
__global__ void __launch_bounds__(GEMM_THREADS, 2)
k_av_t()
{
    const int bx = blockIdx.x, by = blockIdx.y, b = blockIdx.z;
    float acc[4][4][4] = {};
    mma_gemm(d_ah + ((size_t)b * S_LEN + by * 128) * S_LEN,
             d_al + ((size_t)b * S_LEN + by * 128) * S_LEN, S_LEN,
             d_vTh + ((size_t)b * HDIM + bx * 128) * S_LEN,
             d_vTl + ((size_t)b * HDIM + bx * 128) * S_LEN, S_LEN,
             (by + 1) * 4, acc);

    const int lane = threadIdx.x & 31, wid = threadIdx.x >> 5;
    const int g = lane >> 2, tg = lane & 3;
    const int wm = wid & 1, wn = wid >> 1;
#pragma unroll
    for (int mi = 0; mi < 4; ++mi) {
#pragma unroll
        for (int ni = 0; ni < 4; ++ni) {
#pragma unroll
            for (int e = 0; e < 4; ++e) {
                int q = by * 128 + wm * 64 + mi * 16 + g + ((e >> 1) ? 8 : 0);
                int h = bx * 128 + wn * 32 + ni * 8 + tg * 2 + (e & 1);
                size_t idx = ((size_t)q * BSZ + b) * HDIM + h;
                float gv = acc[mi][ni][e] * d_u[idx];
                __nv_bfloat16 gh, gl;
                split2(gv, gh, gl);
                d_gh[idx] = gh;
                d_gl[idx] = gl;
            }
        }
    }
}

// ---------------------------------------------------------------------------
// K4: out = g @ Wo^T + bo
// ---------------------------------------------------------------------------
__global__ void __launch_bounds__(GEMM_THREADS, 2)
k_out_t(const float* __restrict__ ob, float* __restrict__ out)
{
    const int bx = blockIdx.x, by = blockIdx.y;
    float acc[4][4][4] = {};
    mma_gemm(d_gh + (size_t)by * 128 * HDIM, d_gl + (size_t)by * 128 * HDIM, HDIM,
             d_owh + (size_t)bx * 128 * HDIM, d_owl + (size_t)bx * 128 * HDIM, HDIM,
             HDIM / 32, acc);

    const int lane = threadIdx.x & 31, wid = threadIdx.x >> 5;
    const int g = lane >> 2, tg = lane & 3;
    const int wm = wid & 1, wn = wid >> 1;
#pragma unroll
    for (int mi = 0; mi < 4; ++mi) {
#pragma unroll
        for (int ni = 0; ni < 4; ++ni) {
#pragma unroll
            for (int e = 0; e < 4; ++e) {
                int r = by * 128 + wm * 64 + mi * 16 + g + ((e >> 1) ? 8 : 0);
                int c = bx * 128 + wn * 32 + ni * 8 + tg * 2 + (e & 1);
                out[(size_t)r * EDIM + c] = acc[mi][ni][e] + ob[c];
            }
        }
    }
}

// ---------------------------------------------------------------------------
extern "C" void kernel_launch(void* const* d_in, const int* in_sizes, int n_in,
                              void* d_out, int out_size)
{
    const float* x      = (const float*)d_in[0];
    const float* proj_w = (const float*)d_in[2];
    const float* proj_b = (const float*)d_in[3];
    const float* out_w  = (const float*)d_in[4];
    const float* out_b  = (const float*)d_in[5];
    const float* gamma  = (const float*)d_in[6];
    const float* beta   = (const float*)d_in[7];
    const float* rpb    = (const float*)d_in[8];
    float* out = (float*)d_out;

    cudaFuncSetAttribute(k_proj_t, cudaFuncAttributeMaxDynamicSharedMemorySize, SMEM_DYN_BYTES);
    cudaFuncSetAttribute(k_av_t,   cudaFuncAttributeMaxDynamicSharedMemorySize, SMEM_DYN_BYTES);
    cudaFuncSetAttribute(k_out_t,  cudaFuncAttributeMaxDynamicSharedMemorySize, SMEM_DYN_BYTES);

    __nv_bfloat16 *xh, *xl, *pwh, *pwl, *owh, *owl;
    cudaGetSymbolAddress((void**)&xh,  d_xh);
    cudaGetSymbolAddress((void**)&xl,  d_xl);
    cudaGetSymbolAddress((void**)&pwh, d_pwh);
    cudaGetSymbolAddress((void**)&pwl, d_pwl);
    cudaGetSymbolAddress((void**)&owh, d_owh);
    cudaGetSymbolAddress((void**)&owl, d_owl);

    const int nx = S_LEN * BSZ * EDIM;
    const int npw = (2 * HDIM + ZDIM) * EDIM;
    const int now = EDIM * HDIM;
    k_split<<<nx  / 1024, 256>>>(x,      xh,  xl,  nx);
    k_split<<<npw / 1024, 256>>>(proj_w, pwh, pwl, npw);
    k_split<<<now / 1024, 256>>>(out_w,  owh, owl, now);

    k_proj_t<<<dim3(33, 64), dim3(GEMM_THREADS), SMEM_DYN_BYTES>>>(proj_b, gamma, beta);
    k_score <<<dim3(16, 16, 4), dim3(SCORE_THREADS)>>>(rpb);
    k_av_t  <<<dim3(16, 16, 4), dim3(GEMM_THREADS), SMEM_DYN_BYTES>>>();
    k_out_t <<<dim3(8, 64), dim3(GEMM_THREADS), SMEM_DYN_BYTES>>>(out_b, out);
}

// round 15
// speedup vs baseline: 1.3443x; 1.0053x over previous
#include <cuda_runtime.h>
#include <cuda_bf16.h>
#include <cstdint>

// ---------------------------------------------------------------------------
// GatedAttentionUnit: S=2048, B=4, E=1024, Z=128, H=2048
// R15: R14 with a single __syncthreads per chunk: staging for c+1 is issued
//      AFTER the leading barrier (all warps provably done reading that
//      buffer), so the trailing barrier is deleted and wait_group becomes 0.
//      Everything else identical: pre-split bf16 hi/lo global + cp.async
//      2-stage K=32 ring (73.7 KB), 2 CTAs/SM, ldmatrix.x4 fragments,
//      mma.sync bf16 split-2 (hh+hl+lh), fp32 accum.
// ---------------------------------------------------------------------------

#define S_LEN 2048
#define BSZ 4
#define EDIM 1024
#define ZDIM 128
#define HDIM 2048
#define GEMM_THREADS 256
#define SCORE_THREADS 256

// smem stage: A tile + B tile; tile = 128 rows x [hi 16w | lo 16w | pad 4]
// ROW_W = 36 words (144 B: 16B-aligned rows; banks 4r -> ldmatrix conflict-free)
#define ROW_W 36
#define TILE_W (128 * ROW_W)             // 4608 words
#define STAGE_W (2 * TILE_W)             // 9216 words = 36864 B
#define SMEM_DYN_BYTES (2 * STAGE_W * 4) // 73728 B per CTA (container-proven)

// ---------------- scratch (device globals; allocation-free) ----------------
__device__ float d_u [(size_t)S_LEN * BSZ * HDIM];
__device__ float d_q [(size_t)BSZ * S_LEN * ZDIM];
__device__ float d_kk[(size_t)BSZ * S_LEN * ZDIM];

__device__ __nv_bfloat16 d_xh [(size_t)S_LEN * BSZ * EDIM];
__device__ __nv_bfloat16 d_xl [(size_t)S_LEN * BSZ * EDIM];
__device__ __nv_bfloat16 d_pwh[(size_t)(2 * HDIM + ZDIM) * EDIM];
__device__ __nv_bfloat16 d_pwl[(size_t)(2 * HDIM + ZDIM) * EDIM];
__device__ __nv_bfloat16 d_owh[(size_t)EDIM * HDIM];
__device__ __nv_bfloat16 d_owl[(size_t)EDIM * HDIM];
__device__ __nv_bfloat16 d_vTh[(size_t)BSZ * HDIM * S_LEN];
__device__ __nv_bfloat16 d_vTl[(size_t)BSZ * HDIM * S_LEN];
__device__ __nv_bfloat16 d_ah [(size_t)BSZ * S_LEN * S_LEN];
__device__ __nv_bfloat16 d_al [(size_t)BSZ * S_LEN * S_LEN];
__device__ __nv_bfloat16 d_gh [(size_t)S_LEN * BSZ * HDIM];
__device__ __nv_bfloat16 d_gl [(size_t)S_LEN * BSZ * HDIM];

// ---------------------------------------------------------------------------
__device__ __forceinline__ void mma16816(float* d, const uint32_t* a, const uint32_t* b) {
    asm volatile(
        "mma.sync.aligned.m16n8k16.row.col.f32.bf16.bf16.f32 "
        "{%0,%1,%2,%3}, {%4,%5,%6,%7}, {%8,%9}, {%0,%1,%2,%3};"
        : "+f"(d[0]), "+f"(d[1]), "+f"(d[2]), "+f"(d[3])
        : "r"(a[0]), "r"(a[1]), "r"(a[2]), "r"(a[3]), "r"(b[0]), "r"(b[1]));
}

__device__ __forceinline__ void ldm_x4(uint32_t& r0, uint32_t& r1,
                                       uint32_t& r2, uint32_t& r3, uint32_t addr) {
    asm volatile("ldmatrix.sync.aligned.m8n8.x4.shared.b16 {%0,%1,%2,%3}, [%4];"
                 : "=r"(r0), "=r"(r1), "=r"(r2), "=r"(r3) : "r"(addr));
}

__device__ __forceinline__ void split2(float v, __nv_bfloat16& h, __nv_bfloat16& l) {
    h = __float2bfloat16_rn(v);
    l = __float2bfloat16_rn(v - __bfloat162float(h));
}

// ---------------------------------------------------------------------------
// cp.async staging: one K=32 chunk of A and B tiles (hi+lo) = 2048 16B segs;
// 256 threads x 8 segs each.
// ---------------------------------------------------------------------------
__device__ __forceinline__ void stage_chunk(
    const __nv_bfloat16* __restrict__ Ahi, const __nv_bfloat16* __restrict__ Alo, int lda,
    const __nv_bfloat16* __restrict__ Bhi, const __nv_bfloat16* __restrict__ Blo, int ldb,
    int c, uint32_t sbase)
{
    const int tid = threadIdx.x;
#pragma unroll
    for (int u = 0; u < 8; ++u) {
        int seg  = u * GEMM_THREADS + tid;
        int tile = seg >> 10;          // 0 = A, 1 = B
        int s10  = seg & 1023;
        int row  = s10 >> 3;
        int part = s10 & 7;            // 0-3 hi, 4-7 lo
        int p4   = part & 3;
        const __nv_bfloat16* gb;
        int ld;
        if (tile == 0) { gb = (part < 4) ? Ahi : Alo; ld = lda; }
        else           { gb = (part < 4) ? Bhi : Blo; ld = ldb; }
        const void* g = gb + (size_t)row * ld + c * 32 + p4 * 8;
        uint32_t sa = sbase + ((uint32_t)(tile * TILE_W + row * ROW_W
                     + ((part < 4) ? p4 * 4 : 16 + p4 * 4)) << 2);
        asm volatile("cp.async.cg.shared.global [%0], [%1], 16;" :: "r"(sa), "l"(g));
    }
}

// ---------------------------------------------------------------------------
// Core GEMM: acc(128x128) = A(128xK) * B(128xK)^T from pre-split bf16 hi/lo.
// 8 warps as 2(M) x 4(N); per-warp 64x32 via 4x4 m16n8k16 tiles.
// Fragment loads via ldmatrix.x4. Split-2: A-hi(bh,bl) then A-lo(bh).
// 2-stage cp.async pipeline, ONE barrier per chunk; nChunks = K/32 chunks.
// ---------------------------------------------------------------------------
extern __shared__ uint32_t smw[];

__device__ __forceinline__ void mma_gemm(
    const __nv_bfloat16* __restrict__ Ahi, const __nv_bfloat16* __restrict__ Alo, int lda,
    const __nv_bfloat16* __restrict__ Bhi, const __nv_bfloat16* __restrict__ Blo, int ldb,
    int nChunks, float acc[4][4][4])
{
    const int tid = threadIdx.x;
    const int lane = tid & 31, wid = tid >> 5;
    const int wm = wid & 1, wn = wid >> 1;
    uint32_t sb = (uint32_t)__cvta_generic_to_shared(smw);

    // per-thread ldmatrix address offsets (words), relative to tile base
    const int t8 = lane & 7, m4 = lane >> 3;         // m4 = matrix id 0..3
    const int aoffw = (wm * 64 + t8 + (m4 & 1) * 8) * ROW_W + (m4 >> 1) * 4;
    const int boffw = (wn * 32 + t8 + (m4 >> 1) * 8) * ROW_W + (m4 & 1) * 4;

    stage_chunk(Ahi, Alo, lda, Bhi, Blo, ldb, 0, sb);
    asm volatile("cp.async.commit_group;" ::: "memory");

    for (int c = 0; c < nChunks; ++c) {
        asm volatile("cp.async.wait_group 0;" ::: "memory");  // stage c landed
        __syncthreads();   // all warps: stage c visible AND iter c-1 reads done

        // Stage c+1 into the other buffer (safe: its last readers finished
        // iteration c-1, proven by the barrier above). Overlaps MMA below.
        if (c + 1 < nChunks) {
            stage_chunk(Ahi, Alo, lda, Bhi, Blo, ldb, c + 1,
                        sb + (uint32_t)(((c + 1) & 1) * (STAGE_W * 4)));
            asm volatile("cp.async.commit_group;" ::: "memory");
        }

        const uint32_t stg = sb + (uint32_t)((c & 1) * (STAGE_W * 4));
        const uint32_t aB = stg + (uint32_t)(aoffw << 2);
        const uint32_t bB = stg + (uint32_t)((TILE_W + boffw) << 2);
#pragma unroll 1
        for (int ks = 0; ks < 2; ++ks) {
            uint32_t av[4][4], bh[4][2], bl[4][2];
#pragma unroll
            for (int mi = 0; mi < 4; ++mi)     // A-hi
                ldm_x4(av[mi][0], av[mi][1], av[mi][2], av[mi][3],
                       aB + ((mi * 576 + ks * 8) << 2));
#pragma unroll
            for (int np = 0; np < 2; ++np) {   // B-hi / B-lo (2 ni per ldmatrix)
                ldm_x4(bh[2 * np][0], bh[2 * np][1], bh[2 * np + 1][0], bh[2 * np + 1][1],
                       bB + ((np * 576 + ks * 8) << 2));
                ldm_x4(bl[2 * np][0], bl[2 * np][1], bl[2 * np + 1][0], bl[2 * np + 1][1],
                       bB + ((np * 576 + ks * 8 + 16) << 2));
            }
#pragma unroll
            for (int mi = 0; mi < 4; ++mi)
#pragma unroll
                for (int ni = 0; ni < 4; ++ni)
                    mma16816(acc[mi][ni], av[mi], bh[ni]);
#pragma unroll
            for (int mi = 0; mi < 4; ++mi)
#pragma unroll
                for (int ni = 0; ni < 4; ++ni)
                    mma16816(acc[mi][ni], av[mi], bl[ni]);
#pragma unroll
            for (int mi = 0; mi < 4; ++mi)     // A-lo (reuse av regs)
                ldm_x4(av[mi][0], av[mi][1], av[mi][2], av[mi][3],
                       aB + ((mi * 576 + ks * 8 + 16) << 2));
#pragma unroll
            for (int mi = 0; mi < 4; ++mi)
#pragma unroll
                for (int ni = 0; ni < 4; ++ni)
                    mma16816(acc[mi][ni], av[mi], bh[ni]);
        }
    }
}

__device__ __forceinline__ float silu(float v) { return v / (1.0f + __expf(-v)); }

// Per-thread element coordinates inside the 128x128 tile:
//   r = wm*64 + mi*16 + g + (e>=2 ? 8 : 0)
//   c = wn*32 + ni*8 + tg*2 + (e&1)

// ---------------------------------------------------------------------------
// K0: elementwise fp32 -> bf16 hi/lo split (for x, proj_w, out_w)
// ---------------------------------------------------------------------------
__global__ void k_split(const float* __restrict__ src,
                        __nv_bfloat16* __restrict__ hi,
                        __nv_bfloat16* __restrict__ lo, int n)
{
    int i = (blockIdx.x * blockDim.x + threadIdx.x) * 4;
    if (i < n) {
        float4 f = *(const float4*)(src + i);
        __nv_bfloat16 h[4], l[4];
        split2(f.x, h[0], l[0]); split2(f.y, h[1], l[1]);
        split2(f.z, h[2], l[2]); split2(f.w, h[3], l[3]);
        *(uint2*)(hi + i) = *(const uint2*)h;
        *(uint2*)(lo + i) = *(const uint2*)l;
    }
}

// ---------------------------------------------------------------------------
// K1: proj = silu(x @ Wp^T + bp); split into u / vT(hi,lo) / q,k
// ---------------------------------------------------------------------------
__global__ void __launch_bounds__(GEMM_THREADS, 2)
k_proj_t(const float* __restrict__ pb, const float* __restrict__ gamma,
         const float* __restrict__ beta)
{
    const int bx = blockIdx.x, by = blockIdx.y;
    float acc[4][4][4] = {};
    mma_gemm(d_xh + (size_t)by * 128 * EDIM, d_xl + (size_t)by * 128 * EDIM, EDIM,
             d_pwh + (size_t)bx * 128 * EDIM, d_pwl + (size_t)bx * 128 * EDIM, EDIM,
             EDIM / 32, acc);

    const int lane = threadIdx.x & 31, wid = threadIdx.x >> 5;
    const int g = lane >> 2, tg = lane & 3;
    const int wm = wid & 1, wn = wid >> 1;
#pragma unroll
    for (int mi = 0; mi < 4; ++mi) {
#pragma unroll
        for (int ni = 0; ni < 4; ++ni) {
#pragma unroll
            for (int e = 0; e < 4; ++e) {
                int r = by * 128 + wm * 64 + mi * 16 + g + ((e >> 1) ? 8 : 0);
                int cg = bx * 128 + wn * 32 + ni * 8 + tg * 2 + (e & 1);
                float v = silu(acc[mi][ni][e] + pb[cg]);
                int s = r >> 2, b = r & 3;
                if (bx < 16) {
                    d_u[(size_t)r * HDIM + cg] = v;
                } else if (bx < 32) {
                    int h = cg - HDIM;
                    size_t vi = ((size_t)b * HDIM + h) * S_LEN + s;
                    __nv_bfloat16 vh, vl;
                    split2(v, vh, vl);
                    d_vTh[vi] = vh;
                    d_vTl[vi] = vl;
                } else {
                    int zi = cg - 2 * HDIM;
                    size_t qi = ((size_t)b * S_LEN + s) * ZDIM + zi;
                    d_q[qi]  = v * gamma[zi]        + beta[zi];
                    d_kk[qi] = v * gamma[ZDIM + zi] + beta[ZDIM + zi];
                }
            }
        }
    }
}

// ---------------------------------------------------------------------------
// K2: scores = relu(q k^T / S + bias)^2, causal -> attn hi/lo (fp32 FFMA)
// ---------------------------------------------------------------------------
#define BK 16
__global__ void __launch_bounds__(SCORE_THREADS, 2)
k_score(const float* __restrict__ rpb)
{
    const int by = blockIdx.y, bx = blockIdx.x, b = blockIdx.z;
    if (bx > by) return;
    __shared__ float As[BK][129];
    __shared__ float Bs[BK][129];
    float acc[8][8] = {};
    const float* Ag0 = d_q  + ((size_t)b * S_LEN + by * 128) * ZDIM;
    const float* Bg0 = d_kk + ((size_t)b * S_LEN + bx * 128) * ZDIM;
    const int tid = threadIdx.x;
    const int lr = tid >> 2, lc = (tid & 3) << 2;
    const float* Ag = Ag0 + lr * ZDIM + lc;
    const float* Bg = Bg0 + lr * ZDIM + lc;
    const int ty = tid >> 4, tx = tid & 15;
    for (int kk = 0; kk < ZDIM / BK; ++kk) {
        float4 a0 = *(const float4*)(Ag);
        float4 a1 = *(const float4*)(Ag + 64 * ZDIM);
        float4 b0 = *(const float4*)(Bg);
        float4 b1 = *(const float4*)(Bg + 64 * ZDIM);
        __syncthreads();
        As[lc + 0][lr] = a0.x; As[lc + 1][lr] = a0.y; As[lc + 2][lr] = a0.z; As[lc + 3][lr] = a0.w;
        As[lc + 0][lr + 64] = a1.x; As[lc + 1][lr + 64] = a1.y; As[lc + 2][lr + 64] = a1.z; As[lc + 3][lr + 64] = a1.w;
        Bs[lc + 0][lr] = b0.x; Bs[lc + 1][lr] = b0.y; Bs[lc + 2][lr] = b0.z; Bs[lc + 3][lr] = b0.w;
        Bs[lc + 0][lr + 64] = b1.x; Bs[lc + 1][lr + 64] = b1.y; Bs[lc + 2][lr + 64] = b1.z; Bs[lc + 3][lr + 64] = b1.w;
        __syncthreads();
#pragma unroll
        for (int k = 0; k < BK; ++k) {
            float ar[8], br[8];
#pragma unroll
            for (int i = 0; i < 8; ++i) ar[i] = As[k][i * 16 + ty];
#pragma unroll
            for (int j = 0; j < 8; ++j) br[j] = Bs[k][j * 16 + tx];
#pragma unroll
            for (int i = 0; i < 8; ++i)
#pragma unroll
                for (int j = 0; j < 8; ++j) acc[i][j] += ar[i] * br[j];
        }
        Ag += BK; Bg += BK;
    }
#pragma unroll
    for (int i = 0; i < 8; ++i) {
#pragma unroll
        for (int j = 0; j < 8; ++j) {
            int r = by * 128 + i * 16 + ty;
            int c = bx * 128 + j * 16 + tx;
            float v = acc[i][j] * (1.0f / (float)S_LEN) + rpb[(S_LEN - 1) + c - r];
            float a = (c > r) ? 0.0f : fmaxf(v, 0.0f);
            float a2 = a * a;
            size_t idx = ((size_t)b * S_LEN + r) * S_LEN + c;
            __nv_bfloat16 h, l;
            split2(a2, h, l);
            d_ah[idx] = h;
            d_al[idx] = l;
        }
    }
}

// ---------------------------------------------------------------------------
// K3: g = (attn @ v) * u  (K truncated at diagonal) -> g hi/lo
// ---------------------------------------------------------------------------
__global__ void __launch_bounds__(GEMM_THREADS, 2)
k_av_t()
{
    const int bx = blockIdx.x, by = blockIdx.y, b = blockIdx.z;
    float acc[4][4][4] = {};
    mma_gemm(d_ah + ((size_t)b * S_LEN + by * 128) * S_LEN,
             d_al + ((size_t)b * S_LEN + by * 128) * S_LEN, S_LEN,
             d_vTh + ((size_t)b * HDIM + bx * 128) * S_LEN,
             d_vTl + ((size_t)b * HDIM + bx * 128) * S_LEN, S_LEN,
             (by + 1) * 4, acc);

    const int lane = threadIdx.x & 31, wid = threadIdx.x >> 5;
    const int g = lane >> 2, tg = lane & 3;
    const int wm = wid & 1, wn = wid >> 1;
#pragma unroll
    for (int mi = 0; mi < 4; ++mi) {
#pragma unroll
        for (int ni = 0; ni < 4; ++ni) {
#pragma unroll
            for (int e = 0; e < 4; ++e) {
                int q = by * 128 + wm * 64 + mi * 16 + g + ((e >> 1) ? 8 : 0);
                int h = bx * 128 + wn * 32 + ni * 8 + tg * 2 + (e & 1);
                size_t idx = ((size_t)q * BSZ + b) * HDIM + h;
                float gv = acc[mi][ni][e] * d_u[idx];
                __nv_bfloat16 gh, gl;
                split2(gv, gh, gl);
                d_gh[idx] = gh;
                d_gl[idx] = gl;
            }
        }
    }
}

// ---------------------------------------------------------------------------
// K4: out = g @ Wo^T + bo
// ---------------------------------------------------------------------------
__global__ void __launch_bounds__(GEMM_THREADS, 2)
k_out_t(const float* __restrict__ ob, float* __restrict__ out)
{
    const int bx = blockIdx.x, by = blockIdx.y;
    float acc[4][4][4] = {};
    mma_gemm(d_gh + (size_t)by * 128 * HDIM, d_gl + (size_t)by * 128 * HDIM, HDIM,
             d_owh + (size_t)bx * 128 * HDIM, d_owl + (size_t)bx * 128 * HDIM, HDIM,
             HDIM / 32, acc);

    const int lane = threadIdx.x & 31, wid = threadIdx.x >> 5;
    const int g = lane >> 2, tg = lane & 3;
    const int wm = wid & 1, wn = wid >> 1;
#pragma unroll
    for (int mi = 0; mi < 4; ++mi) {
#pragma unroll
        for (int ni = 0; ni < 4; ++ni) {
#pragma unroll
            for (int e = 0; e < 4; ++e) {
                int r = by * 128 + wm * 64 + mi * 16 + g + ((e >> 1) ? 8 : 0);
                int c = bx * 128 + wn * 32 + ni * 8 + tg * 2 + (e & 1);
                out[(size_t)r * EDIM + c] = acc[mi][ni][e] + ob[c];
            }
        }
    }
}

// ---------------------------------------------------------------------------
extern "C" void kernel_launch(void* const* d_in, const int* in_sizes, int n_in,
                              void* d_out, int out_size)
{
    const float* x      = (const float*)d_in[0];
    const float* proj_w = (const float*)d_in[2];
    const float* proj_b = (const float*)d_in[3];
    const float* out_w  = (const float*)d_in[4];
    const float* out_b  = (const float*)d_in[5];
    const float* gamma  = (const float*)d_in[6];
    const float* beta   = (const float*)d_in[7];
    const float* rpb    = (const float*)d_in[8];
    float* out = (float*)d_out;

    cudaFuncSetAttribute(k_proj_t, cudaFuncAttributeMaxDynamicSharedMemorySize, SMEM_DYN_BYTES);
    cudaFuncSetAttribute(k_av_t,   cudaFuncAttributeMaxDynamicSharedMemorySize, SMEM_DYN_BYTES);
    cudaFuncSetAttribute(k_out_t,  cudaFuncAttributeMaxDynamicSharedMemorySize, SMEM_DYN_BYTES);

    __nv_bfloat16 *xh, *xl, *pwh, *pwl, *owh, *owl;
    cudaGetSymbolAddress((void**)&xh,  d_xh);
    cudaGetSymbolAddress((void**)&xl,  d_xl);
    cudaGetSymbolAddress((void**)&pwh, d_pwh);
    cudaGetSymbolAddress((void**)&pwl, d_pwl);
    cudaGetSymbolAddress((void**)&owh, d_owh);
    cudaGetSymbolAddress((void**)&owl, d_owl);

    const int nx = S_LEN * BSZ * EDIM;
    const int npw = (2 * HDIM + ZDIM) * EDIM;
    const int now = EDIM * HDIM;
    k_split<<<nx  / 1024, 256>>>(x,      xh,  xl,  nx);
    k_split<<<npw / 1024, 256>>>(proj_w, pwh, pwl, npw);
    k_split<<<now / 1024, 256>>>(out_w,  owh, owl, now);

    k_proj_t<<<dim3(33, 64), dim3(GEMM_THREADS), SMEM_DYN_BYTES>>>(proj_b, gamma, beta);
    k_score <<<dim3(16, 16, 4), dim3(SCORE_THREADS)>>>(rpb);
    k_av_t  <<<dim3(16, 16, 4), dim3(GEMM_THREADS), SMEM_DYN_BYTES>>>();
    k_out_t <<<dim3(8, 64), dim3(GEMM_THREADS), SMEM_DYN_BYTES>>>(out_b, out);
}